// round 11
// baseline (speedup 1.0000x reference)
#include <cuda_runtime.h>
#include <cuda_fp16.h>
#include <mma.h>
#include <math.h>
using namespace nvcuda;

#define N_NODES 50000
#define E_EDGES 800000
#define ET      (E_EDGES + N_NODES)   // 850000 edges incl. self loops
#define F_IN    128
#define H1      4
#define C1      64
#define HC1     256
#define C2      64
#define NEG_SLOPE 0.2f
#define EPS_DEN 1e-16f
#define SCAN_B  1024
#define NBLK    ((N_NODES + SCAN_B - 1) / SCAN_B)   // 49

// ---------------- scratch (device globals; 16B-aligned) ----------------------
__device__ __align__(16) __half g_h1h[N_NODES * HC1];   // layer1 features (fp16)
__device__ __align__(16) float  g_x2 [N_NODES * HC1];   // elu(agg1+b1), fp32
__device__ __align__(16) __half g_h2h[N_NODES * C2];    // layer2 features (fp16)
__device__ __align__(16) __half g_W1h[F_IN * HC1];      // split weights
__device__ __align__(16) __half g_W1l[F_IN * HC1];
__device__ __align__(16) __half g_W2h[HC1 * C2];
__device__ __align__(16) __half g_W2l[HC1 * C2];
__device__ __align__(16) float  g_as1[N_NODES * H1];
__device__ __align__(16) float  g_ad1[N_NODES * H1];
__device__ __align__(16) float  g_as2[N_NODES];
__device__ __align__(16) float  g_ad2[N_NODES];
__device__ __align__(16) float  g_alpha1[ET * H1];
__device__ __align__(16) float  g_alpha2[ET];
__device__ __align__(16) int    g_src[ET];
__device__ __align__(16) int    g_dst[ET];
__device__ __align__(16) int    g_csr_src[ET];
__device__ __align__(16) int    g_rowptr[N_NODES + 1];
__device__ __align__(16) int    g_cursor[N_NODES];
__device__ __align__(16) int    g_deg[N_NODES];
__device__ __align__(16) int    g_bsum[NBLK];
__device__ __align__(16) int    g_boff[NBLK];
__device__ int g_is64;

// ---------------- helpers ----------------------------------------------------
__device__ __forceinline__ int clampN(int v) {
    return v < 0 ? 0 : (v >= N_NODES ? N_NODES - 1 : v);
}
__device__ __forceinline__ float lrelu(float v) {
    return v > 0.f ? v : NEG_SLOPE * v;
}

// ---------------- prep: split weights into fp16 hi/lo -------------------------
__global__ void prep_kernel(const float* __restrict__ W1, const float* __restrict__ W2) {
    int i = blockIdx.x * blockDim.x + threadIdx.x;
    if (i < F_IN * HC1) {
        float v = W1[i];
        __half h = __float2half_rn(v);
        g_W1h[i] = h;
        g_W1l[i] = __float2half_rn(v - __half2float(h));
    }
    int j = i - F_IN * HC1;
    if (j >= 0 && j < HC1 * C2) {
        float v = W2[j];
        __half h = __float2half_rn(v);
        g_W2h[j] = h;
        g_W2l[j] = __float2half_rn(v - __half2float(h));
    }
}

// ---------------- detect dtype + zero degree ----------------------------------
__global__ void detzero_kernel(const int* __restrict__ ei32) {
    int i = blockIdx.x * blockDim.x + threadIdx.x;
    if (i < N_NODES) g_deg[i] = 0;
    if (blockIdx.x == 0 && threadIdx.x < 32) {
        int lane = threadIdx.x;
        int v = ei32[2 * lane + 1] | ei32[2 * (lane + 32) + 1] |
                ei32[2 * (lane + 64) + 1] | ei32[2 * (lane + 96) + 1];
#pragma unroll
        for (int o = 16; o; o >>= 1) v |= __shfl_xor_sync(0xFFFFFFFFu, v, o);
        if (lane == 0) g_is64 = (v == 0) ? 1 : 0;
    }
}

__global__ void edges_kernel(const void* __restrict__ ei) {
    int i = blockIdx.x * blockDim.x + threadIdx.x;
    if (i >= ET) return;
    int s, d;
    if (i < E_EDGES) {
        if (g_is64) {
            const long long* p = (const long long*)ei;
            s = (int)p[i];  d = (int)p[E_EDGES + i];
        } else {
            const int* p = (const int*)ei;
            s = p[i];  d = p[E_EDGES + i];
        }
        s = clampN(s); d = clampN(d);
    } else {
        s = d = i - E_EDGES;
    }
    g_src[i] = s;
    g_dst[i] = d;
    atomicAdd(&g_deg[d], 1);
}

// ---------------- 3-phase parallel scan of g_deg -> g_rowptr ------------------
__global__ __launch_bounds__(SCAN_B) void scan_partial_kernel() {
    __shared__ int red[32];
    int i = blockIdx.x * SCAN_B + threadIdx.x;
    int v = (i < N_NODES) ? g_deg[i] : 0;
#pragma unroll
    for (int o = 16; o; o >>= 1) v += __shfl_down_sync(0xFFFFFFFFu, v, o);
    if ((threadIdx.x & 31) == 0) red[threadIdx.x >> 5] = v;
    __syncthreads();
    if (threadIdx.x < 32) {
        int r = red[threadIdx.x];
#pragma unroll
        for (int o = 16; o; o >>= 1) r += __shfl_down_sync(0xFFFFFFFFu, r, o);
        if (threadIdx.x == 0) g_bsum[blockIdx.x] = r;
    }
}

__global__ void scan_tops_kernel() {
    int lane = threadIdx.x;
    int v0 = (lane < NBLK) ? g_bsum[lane] : 0;
    int v1 = (lane + 32 < NBLK) ? g_bsum[lane + 32] : 0;
    int a = v0;
#pragma unroll
    for (int o = 1; o < 32; o <<= 1) {
        int t = __shfl_up_sync(0xFFFFFFFFu, a, o);
        if (lane >= o) a += t;
    }
    int tot0 = __shfl_sync(0xFFFFFFFFu, a, 31);
    int b = v1;
#pragma unroll
    for (int o = 1; o < 32; o <<= 1) {
        int t = __shfl_up_sync(0xFFFFFFFFu, b, o);
        if (lane >= o) b += t;
    }
    b += tot0;
    if (lane < NBLK) g_boff[lane] = a - v0;
    if (lane + 32 < NBLK) g_boff[lane + 32] = b - v1;
    if (lane == 31) g_rowptr[N_NODES] = (NBLK > 32) ? __shfl_sync(0xFFFFFFFFu, b, 31)
                                                    : tot0;
}

__global__ __launch_bounds__(SCAN_B) void scan_final_kernel() {
    __shared__ int warp_tot[32];
    int i = blockIdx.x * SCAN_B + threadIdx.x;
    int v = (i < N_NODES) ? g_deg[i] : 0;
    int lane = threadIdx.x & 31, w = threadIdx.x >> 5;
    int a = v;
#pragma unroll
    for (int o = 1; o < 32; o <<= 1) {
        int t = __shfl_up_sync(0xFFFFFFFFu, a, o);
        if (lane >= o) a += t;
    }
    if (lane == 31) warp_tot[w] = a;
    __syncthreads();
    if (threadIdx.x < 32) {
        int t = warp_tot[threadIdx.x];
        int s = t;
#pragma unroll
        for (int o = 1; o < 32; o <<= 1) {
            int u = __shfl_up_sync(0xFFFFFFFFu, s, o);
            if (threadIdx.x >= o) s += u;
        }
        warp_tot[threadIdx.x] = s - t;
    }
    __syncthreads();
    int excl = a - v + warp_tot[w] + g_boff[blockIdx.x];
    if (i < N_NODES) { g_rowptr[i] = excl; g_cursor[i] = excl; }
}

__global__ void scatter_kernel() {
    int i = blockIdx.x * blockDim.x + threadIdx.x;
    if (i >= ET) return;
    int pos = atomicAdd(&g_cursor[g_dst[i]], 1);
    g_csr_src[pos] = g_src[i];
}

// ---------------- split-fp16 tensor-core GEMM ---------------------------------
// C[M,NOUT] = A[M,K] @ B[K,NOUT] with A fp32 (split on the fly) and B pre-split
// fp16 hi/lo.  C ~= Ah*Bh + Al*Bh + Ah*Bl (fp32 accumulate) -> ~1e-6 rel err.
// Writes ONLY the fp16 mirror Ch plus per-(row,head) attention logits AS/AD
// (direct stores; each block owns its heads).
template<int K, int NOUT, int BN>
__global__ __launch_bounds__(256)
void hgemm_kernel(const float* __restrict__ A,
                  const __half* __restrict__ Bh, const __half* __restrict__ Bl,
                  __half* __restrict__ Ch,
                  const float* __restrict__ att_s, const float* __restrict__ att_d,
                  float* __restrict__ AS, float* __restrict__ AD, int M) {
    constexpr int BM = 128, BK = 16;
    constexpr int WCOLS = BN / 64;            // 2 (BN=128) or 1 (BN=64)
    constexpr int WROWS = 8 / WCOLS;          // 4 or 8
    constexpr int WM = BM / WROWS;            // 32 or 16
    constexpr int FM = WM / 16;               // 2 or 1
    constexpr int HEADS = NOUT / 64;

    extern __shared__ char smem[];
    half* sAh = (half*)smem;                  // [BM][BK]
    half* sAl = sAh + BM * BK;
    half* sBh = sAl + BM * BK;                // [BK][BN]
    half* sBl = sBh + BK * BN;
    float* Cs = (float*)smem;                 // [BM][BN] (reused after k-loop)

    int t = threadIdx.x, wid = t >> 5;
    int wr = wid % WROWS, wc = wid / WROWS;
    int warpM = wr * WM, warpN = wc * 64;
    int rowBase = blockIdx.y * BM, colBase = blockIdx.x * BN;

    wmma::fragment<wmma::accumulator, 16, 16, 16, float> acc[FM][4];
#pragma unroll
    for (int i = 0; i < FM; i++)
#pragma unroll
        for (int j = 0; j < 4; j++) wmma::fill_fragment(acc[i][j], 0.f);

    for (int kt = 0; kt < K; kt += BK) {
        // A tile: 128x16 fp32 -> split halves. thread: row t>>1, 8-col chunk.
        {
            int r = t >> 1, c8 = (t & 1) * 8;
            int gr = rowBase + r;
            float va[8] = {0.f, 0.f, 0.f, 0.f, 0.f, 0.f, 0.f, 0.f};
            if (gr < M) {
                float4 v0 = *(const float4*)&A[(size_t)gr * K + kt + c8];
                float4 v1 = *(const float4*)&A[(size_t)gr * K + kt + c8 + 4];
                va[0] = v0.x; va[1] = v0.y; va[2] = v0.z; va[3] = v0.w;
                va[4] = v1.x; va[5] = v1.y; va[6] = v1.z; va[7] = v1.w;
            }
#pragma unroll
            for (int i = 0; i < 8; i++) {
                __half h = __float2half_rn(va[i]);
                sAh[r * BK + c8 + i] = h;
                sAl[r * BK + c8 + i] = __float2half_rn(va[i] - __half2float(h));
            }
        }
        // B tile: 16xBN halves (hi+lo), 8 halves per thread
        if (t < 2 * BN) {
            int br = t / (BN / 8);
            int bc = (t % (BN / 8)) * 8;
            *(uint4*)&sBh[br * BN + bc] =
                *(const uint4*)&Bh[(size_t)(kt + br) * NOUT + colBase + bc];
            *(uint4*)&sBl[br * BN + bc] =
                *(const uint4*)&Bl[(size_t)(kt + br) * NOUT + colBase + bc];
        }
        __syncthreads();

        wmma::fragment<wmma::matrix_a, 16, 16, 16, half, wmma::row_major> ah[FM], al[FM];
#pragma unroll
        for (int i = 0; i < FM; i++) {
            wmma::load_matrix_sync(ah[i], sAh + (warpM + i * 16) * BK, BK);
            wmma::load_matrix_sync(al[i], sAl + (warpM + i * 16) * BK, BK);
        }
#pragma unroll
        for (int j = 0; j < 4; j++) {
            wmma::fragment<wmma::matrix_b, 16, 16, 16, half, wmma::row_major> bh, bl;
            wmma::load_matrix_sync(bh, sBh + warpN + j * 16, BN);
            wmma::load_matrix_sync(bl, sBl + warpN + j * 16, BN);
#pragma unroll
            for (int i = 0; i < FM; i++) {
                wmma::mma_sync(acc[i][j], ah[i], bh, acc[i][j]);
                wmma::mma_sync(acc[i][j], al[i], bh, acc[i][j]);
                wmma::mma_sync(acc[i][j], ah[i], bl, acc[i][j]);
            }
        }
        __syncthreads();
    }

    // stage fp32 C tile in shared
#pragma unroll
    for (int i = 0; i < FM; i++)
#pragma unroll
        for (int j = 0; j < 4; j++)
            wmma::store_matrix_sync(Cs + (warpM + i * 16) * BN + warpN + j * 16,
                                    acc[i][j], BN, wmma::mem_row_major);
    __syncthreads();

    // convert + store fp16 mirror (coalesced half2 writes)
    {
        constexpr int RPI = 512 / BN;         // rows per iteration
        int cr = t / (BN / 2), cc = t % (BN / 2);
        for (int r0 = 0; r0 < BM; r0 += RPI) {
            int r = r0 + cr, gr = rowBase + r;
            if (gr < M) {
                float x0 = Cs[r * BN + 2 * cc];
                float x1 = Cs[r * BN + 2 * cc + 1];
                *(__half2*)&Ch[(size_t)gr * NOUT + colBase + 2 * cc] =
                    __floats2half2_rn(x0, x1);
            }
        }
    }
    // attention logits from the staged tile (direct stores, no atomics)
    if (t < BM) {
        int n = rowBase + t;
        if (n < M) {
#pragma unroll
            for (int hl = 0; hl < BN / 64; hl++) {
                int head = colBase / 64 + hl;
                const float* Sv = att_s + head * 64;
                const float* Dv = att_d + head * 64;
                const float* row = Cs + t * BN + hl * 64;
                float s = 0.f, d = 0.f;
#pragma unroll
                for (int c = 0; c < 64; c++) {
                    s += row[c] * Sv[c];
                    d += row[c] * Dv[c];
                }
                AS[n * HEADS + head] = s;
                AD[n * HEADS + head] = d;
            }
        }
    }
}

// ---------------- per-node softmax (warp per node), writes alpha -------------
__global__ void softmax1_kernel() {
    int w = (blockIdx.x * blockDim.x + threadIdx.x) >> 5;
    int lane = threadIdx.x & 31;
    if (w >= N_NODES) return;
    int lo = g_rowptr[w], hi = g_rowptr[w + 1];
    float4 ad = *(const float4*)&g_ad1[w * 4];
    float m0 = -1e30f, m1 = -1e30f, m2 = -1e30f, m3 = -1e30f;
    float s0 = 0.f, s1 = 0.f, s2 = 0.f, s3 = 0.f;
    for (int k = lo + lane; k < hi; k += 32) {
        int s = g_csr_src[k];
        float4 as = *(const float4*)&g_as1[s * 4];
        float v0 = lrelu(as.x + ad.x), v1 = lrelu(as.y + ad.y);
        float v2 = lrelu(as.z + ad.z), v3 = lrelu(as.w + ad.w);
        if (v0 > m0) { s0 *= __expf(m0 - v0); m0 = v0; }  s0 += __expf(v0 - m0);
        if (v1 > m1) { s1 *= __expf(m1 - v1); m1 = v1; }  s1 += __expf(v1 - m1);
        if (v2 > m2) { s2 *= __expf(m2 - v2); m2 = v2; }  s2 += __expf(v2 - m2);
        if (v3 > m3) { s3 *= __expf(m3 - v3); m3 = v3; }  s3 += __expf(v3 - m3);
    }
#pragma unroll
    for (int off = 16; off; off >>= 1) {
        float mo, so, mn;
        mo = __shfl_xor_sync(0xFFFFFFFFu, m0, off); so = __shfl_xor_sync(0xFFFFFFFFu, s0, off);
        mn = fmaxf(m0, mo); s0 = s0 * __expf(m0 - mn) + so * __expf(mo - mn); m0 = mn;
        mo = __shfl_xor_sync(0xFFFFFFFFu, m1, off); so = __shfl_xor_sync(0xFFFFFFFFu, s1, off);
        mn = fmaxf(m1, mo); s1 = s1 * __expf(m1 - mn) + so * __expf(mo - mn); m1 = mn;
        mo = __shfl_xor_sync(0xFFFFFFFFu, m2, off); so = __shfl_xor_sync(0xFFFFFFFFu, s2, off);
        mn = fmaxf(m2, mo); s2 = s2 * __expf(m2 - mn) + so * __expf(mo - mn); m2 = mn;
        mo = __shfl_xor_sync(0xFFFFFFFFu, m3, off); so = __shfl_xor_sync(0xFFFFFFFFu, s3, off);
        mn = fmaxf(m3, mo); s3 = s3 * __expf(m3 - mn) + so * __expf(mo - mn); m3 = mn;
    }
    float i0 = 1.f / (s0 + EPS_DEN), i1 = 1.f / (s1 + EPS_DEN);
    float i2 = 1.f / (s2 + EPS_DEN), i3 = 1.f / (s3 + EPS_DEN);
    for (int k = lo + lane; k < hi; k += 32) {
        int s = g_csr_src[k];
        float4 as = *(const float4*)&g_as1[s * 4];
        float a0 = __expf(lrelu(as.x + ad.x) - m0) * i0;
        float a1 = __expf(lrelu(as.y + ad.y) - m1) * i1;
        float a2 = __expf(lrelu(as.z + ad.z) - m2) * i2;
        float a3 = __expf(lrelu(as.w + ad.w) - m3) * i3;
        *(float4*)&g_alpha1[k * 4] = make_float4(a0, a1, a2, a3);
    }
}

__global__ void softmax2_kernel() {
    int w = (blockIdx.x * blockDim.x + threadIdx.x) >> 5;
    int lane = threadIdx.x & 31;
    if (w >= N_NODES) return;
    int lo = g_rowptr[w], hi = g_rowptr[w + 1];
    float ad = g_ad2[w];
    float m = -1e30f, s = 0.f;
    for (int k = lo + lane; k < hi; k += 32) {
        float v = lrelu(g_as2[g_csr_src[k]] + ad);
        if (v > m) { s *= __expf(m - v); m = v; }
        s += __expf(v - m);
    }
#pragma unroll
    for (int off = 16; off; off >>= 1) {
        float mo = __shfl_xor_sync(0xFFFFFFFFu, m, off);
        float so = __shfl_xor_sync(0xFFFFFFFFu, s, off);
        float mn = fmaxf(m, mo);
        s = s * __expf(m - mn) + so * __expf(mo - mn);
        m = mn;
    }
    float inv = 1.f / (s + EPS_DEN);
    for (int k = lo + lane; k < hi; k += 32) {
        float v = lrelu(g_as2[g_csr_src[k]] + ad);
        g_alpha2[k] = __expf(v - m) * inv;
    }
}

// ---------------- aggregation (fp16 half2 gathers, 4-way unroll) --------------
__global__ __launch_bounds__(128)
void agg1_kernel(const float* __restrict__ b1) {
    int n = blockIdx.x;
    int c2 = threadIdx.x;
    int h = c2 >> 5;
    int lo = g_rowptr[n], hi = g_rowptr[n + 1];
    const __half2* H = (const __half2*)g_h1h;
    float ax = 0.f, ay = 0.f, bx = 0.f, by = 0.f;
    float cx = 0.f, cy = 0.f, dx = 0.f, dy = 0.f;
    int k = lo;
    for (; k + 3 < hi; k += 4) {
        int s0 = g_csr_src[k],     s1 = g_csr_src[k + 1];
        int s2 = g_csr_src[k + 2], s3 = g_csr_src[k + 3];
        float a0 = g_alpha1[k * 4 + h],       a1 = g_alpha1[(k + 1) * 4 + h];
        float a2 = g_alpha1[(k + 2) * 4 + h], a3 = g_alpha1[(k + 3) * 4 + h];
        float2 v0 = __half22float2(__ldg(&H[(size_t)s0 * 128 + c2]));
        float2 v1 = __half22float2(__ldg(&H[(size_t)s1 * 128 + c2]));
        float2 v2 = __half22float2(__ldg(&H[(size_t)s2 * 128 + c2]));
        float2 v3 = __half22float2(__ldg(&H[(size_t)s3 * 128 + c2]));
        ax += a0 * v0.x; ay += a0 * v0.y;
        bx += a1 * v1.x; by += a1 * v1.y;
        cx += a2 * v2.x; cy += a2 * v2.y;
        dx += a3 * v3.x; dy += a3 * v3.y;
    }
    for (; k < hi; k++) {
        int s0 = g_csr_src[k];
        float a0 = g_alpha1[k * 4 + h];
        float2 v0 = __half22float2(__ldg(&H[(size_t)s0 * 128 + c2]));
        ax += a0 * v0.x; ay += a0 * v0.y;
    }
    float vx = (ax + bx) + (cx + dx) + b1[2 * c2];
    float vy = (ay + by) + (cy + dy) + b1[2 * c2 + 1];
    float2 r;
    r.x = vx > 0.f ? vx : expm1f(vx);
    r.y = vy > 0.f ? vy : expm1f(vy);
    *(float2*)&g_x2[(size_t)n * HC1 + 2 * c2] = r;
}

__global__ __launch_bounds__(64)
void agg2_kernel(float* __restrict__ out, const float* __restrict__ b2) {
    int n = blockIdx.x * 2 + (threadIdx.x >> 5);
    if (n >= N_NODES) return;
    int c2 = threadIdx.x & 31;
    int lo = g_rowptr[n], hi = g_rowptr[n + 1];
    const __half2* H = (const __half2*)g_h2h;
    float ax = 0.f, ay = 0.f, bx = 0.f, by = 0.f;
    float cx = 0.f, cy = 0.f, dx = 0.f, dy = 0.f;
    int k = lo;
    for (; k + 3 < hi; k += 4) {
        int s0 = g_csr_src[k],     s1 = g_csr_src[k + 1];
        int s2 = g_csr_src[k + 2], s3 = g_csr_src[k + 3];
        float a0 = g_alpha2[k],     a1 = g_alpha2[k + 1];
        float a2 = g_alpha2[k + 2], a3 = g_alpha2[k + 3];
        float2 v0 = __half22float2(__ldg(&H[(size_t)s0 * 32 + c2]));
        float2 v1 = __half22float2(__ldg(&H[(size_t)s1 * 32 + c2]));
        float2 v2 = __half22float2(__ldg(&H[(size_t)s2 * 32 + c2]));
        float2 v3 = __half22float2(__ldg(&H[(size_t)s3 * 32 + c2]));
        ax += a0 * v0.x; ay += a0 * v0.y;
        bx += a1 * v1.x; by += a1 * v1.y;
        cx += a2 * v2.x; cy += a2 * v2.y;
        dx += a3 * v3.x; dy += a3 * v3.y;
    }
    for (; k < hi; k++) {
        int s0 = g_csr_src[k];
        float a0 = g_alpha2[k];
        float2 v0 = __half22float2(__ldg(&H[(size_t)s0 * 32 + c2]));
        ax += a0 * v0.x; ay += a0 * v0.y;
    }
    float2 r;
    r.x = (ax + bx) + (cx + dx) + b2[2 * c2];
    r.y = (ay + by) + (cy + dy) + b2[2 * c2 + 1];
    *(float2*)&out[(size_t)n * C2 + 2 * c2] = r;
}

// ---------------- launch ------------------------------------------------------
static inline int cdiv(long long a, int b) { return (int)((a + b - 1) / b); }

extern "C" void kernel_launch(void* const* d_in, const int* in_sizes, int n_in,
                              void* d_out, int out_size) {
    const float* x        = (const float*)d_in[0];
    const void*  ei       = d_in[1];
    const float* W1       = (const float*)d_in[2];
    const float* att_src1 = (const float*)d_in[3];
    const float* att_dst1 = (const float*)d_in[4];
    const float* b1       = (const float*)d_in[5];
    const float* W2       = (const float*)d_in[6];
    const float* att_src2 = (const float*)d_in[7];
    const float* att_dst2 = (const float*)d_in[8];
    const float* b2       = (const float*)d_in[9];
    float* out = (float*)d_out;

    float *x2, *as1, *ad1, *as2, *ad2;
    __half *h1h, *h2h, *w1h, *w1l, *w2h, *w2l;
    cudaGetSymbolAddress((void**)&x2, g_x2);
    cudaGetSymbolAddress((void**)&h1h, g_h1h);
    cudaGetSymbolAddress((void**)&h2h, g_h2h);
    cudaGetSymbolAddress((void**)&as1, g_as1);
    cudaGetSymbolAddress((void**)&ad1, g_ad1);
    cudaGetSymbolAddress((void**)&as2, g_as2);
    cudaGetSymbolAddress((void**)&ad2, g_ad2);
    cudaGetSymbolAddress((void**)&w1h, g_W1h);
    cudaGetSymbolAddress((void**)&w1l, g_W1l);
    cudaGetSymbolAddress((void**)&w2h, g_W2h);
    cudaGetSymbolAddress((void**)&w2l, g_W2l);

    const int T = 256;
    const int SMEM1 = 128 * 128 * 4;    // 64KB staging (>= tile region)
    const int SMEM2 = 128 * 64 * 4;     // 32KB

    cudaFuncSetAttribute(hgemm_kernel<F_IN, HC1, 128>,
                         cudaFuncAttributeMaxDynamicSharedMemorySize, SMEM1);

    prep_kernel<<<cdiv(F_IN * HC1 + HC1 * C2, T), T>>>(W1, W2);     // #1
    detzero_kernel<<<cdiv(N_NODES, T), T>>>((const int*)ei);        // #2
    edges_kernel<<<cdiv(ET, T), T>>>(ei);                           // #3
    // #4: hgemm1 — profiled next round
    {
        dim3 grid(HC1 / 128, cdiv(N_NODES, 128));
        hgemm_kernel<F_IN, HC1, 128><<<grid, T, SMEM1>>>(
            x, w1h, w1l, h1h, att_src1, att_dst1, as1, ad1, N_NODES);
    }
    scan_partial_kernel<<<NBLK, SCAN_B>>>();
    scan_tops_kernel<<<1, 32>>>();
    scan_final_kernel<<<NBLK, SCAN_B>>>();
    scatter_kernel<<<cdiv(ET, T), T>>>();
    softmax1_kernel<<<cdiv((long long)N_NODES * 32, T), T>>>();
    agg1_kernel<<<N_NODES, 128>>>(b1);
    {
        dim3 grid(1, cdiv(N_NODES, 128));
        hgemm_kernel<HC1, C2, 64><<<grid, T, SMEM2>>>(
            x2, w2h, w2l, h2h, att_src2, att_dst2, as2, ad2, N_NODES);
    }
    softmax2_kernel<<<cdiv((long long)N_NODES * 32, T), T>>>();
    agg2_kernel<<<cdiv(N_NODES, 2), 64>>>(out, b2);
}

// round 12
// speedup vs baseline: 1.1460x; 1.1460x over previous
#include <cuda_runtime.h>
#include <cuda_fp16.h>
#include <mma.h>
#include <math.h>
using namespace nvcuda;

#define N_NODES 50000
#define E_EDGES 800000
#define ET      (E_EDGES + N_NODES)   // 850000 edges incl. self loops
#define F_IN    128
#define H1      4
#define C1      64
#define HC1     256
#define C2      64
#define NEG_SLOPE 0.2f
#define EPS_DEN 1e-16f
#define SCAN_B  1024
#define NBLK    ((N_NODES + SCAN_B - 1) / SCAN_B)   // 49

// ---------------- scratch (device globals; 16B-aligned) ----------------------
__device__ __align__(16) __half g_h1h[N_NODES * HC1];   // layer1 features (fp16)
__device__ __align__(16) float  g_x2 [N_NODES * HC1];   // elu(agg1+b1), fp32
__device__ __align__(16) __half g_h2h[N_NODES * C2];    // layer2 features (fp16)
__device__ __align__(16) __half g_W1h[F_IN * HC1];      // split weights
__device__ __align__(16) __half g_W1l[F_IN * HC1];
__device__ __align__(16) __half g_W2h[HC1 * C2];
__device__ __align__(16) __half g_W2l[HC1 * C2];
__device__ __align__(16) float  g_as1[N_NODES * H1];
__device__ __align__(16) float  g_ad1[N_NODES * H1];
__device__ __align__(16) float  g_as2[N_NODES];
__device__ __align__(16) float  g_ad2[N_NODES];
__device__ __align__(16) float  g_alpha1[ET * H1];
__device__ __align__(16) float  g_alpha2[ET];
__device__ __align__(16) int    g_src[ET];
__device__ __align__(16) int    g_dst[ET];
__device__ __align__(16) int    g_csr_src[ET];
__device__ __align__(16) int    g_rowptr[N_NODES + 1];
__device__ __align__(16) int    g_cursor[N_NODES];
__device__ __align__(16) int    g_deg[N_NODES];
__device__ __align__(16) int    g_bsum[NBLK];
__device__ __align__(16) int    g_boff[NBLK];
__device__ int g_is64;

// ---------------- helpers ----------------------------------------------------
__device__ __forceinline__ int clampN(int v) {
    return v < 0 ? 0 : (v >= N_NODES ? N_NODES - 1 : v);
}
__device__ __forceinline__ float lrelu(float v) {
    return v > 0.f ? v : NEG_SLOPE * v;
}

// ---------------- prep: split weights into fp16 hi/lo -------------------------
__global__ void prep_kernel(const float* __restrict__ W1, const float* __restrict__ W2) {
    int i = blockIdx.x * blockDim.x + threadIdx.x;
    if (i < F_IN * HC1) {
        float v = W1[i];
        __half h = __float2half_rn(v);
        g_W1h[i] = h;
        g_W1l[i] = __float2half_rn(v - __half2float(h));
    }
    int j = i - F_IN * HC1;
    if (j >= 0 && j < HC1 * C2) {
        float v = W2[j];
        __half h = __float2half_rn(v);
        g_W2h[j] = h;
        g_W2l[j] = __float2half_rn(v - __half2float(h));
    }
}

// ---------------- detect dtype + zero degree ----------------------------------
__global__ void detzero_kernel(const int* __restrict__ ei32) {
    int i = blockIdx.x * blockDim.x + threadIdx.x;
    if (i < N_NODES) g_deg[i] = 0;
    if (blockIdx.x == 0 && threadIdx.x < 32) {
        int lane = threadIdx.x;
        int v = ei32[2 * lane + 1] | ei32[2 * (lane + 32) + 1] |
                ei32[2 * (lane + 64) + 1] | ei32[2 * (lane + 96) + 1];
#pragma unroll
        for (int o = 16; o; o >>= 1) v |= __shfl_xor_sync(0xFFFFFFFFu, v, o);
        if (lane == 0) g_is64 = (v == 0) ? 1 : 0;
    }
}

__global__ void edges_kernel(const void* __restrict__ ei) {
    int i = blockIdx.x * blockDim.x + threadIdx.x;
    if (i >= ET) return;
    int s, d;
    if (i < E_EDGES) {
        if (g_is64) {
            const long long* p = (const long long*)ei;
            s = (int)p[i];  d = (int)p[E_EDGES + i];
        } else {
            const int* p = (const int*)ei;
            s = p[i];  d = p[E_EDGES + i];
        }
        s = clampN(s); d = clampN(d);
    } else {
        s = d = i - E_EDGES;
    }
    g_src[i] = s;
    g_dst[i] = d;
    atomicAdd(&g_deg[d], 1);
}

// ---------------- 3-phase parallel scan of g_deg -> g_rowptr ------------------
__global__ __launch_bounds__(SCAN_B) void scan_partial_kernel() {
    __shared__ int red[32];
    int i = blockIdx.x * SCAN_B + threadIdx.x;
    int v = (i < N_NODES) ? g_deg[i] : 0;
#pragma unroll
    for (int o = 16; o; o >>= 1) v += __shfl_down_sync(0xFFFFFFFFu, v, o);
    if ((threadIdx.x & 31) == 0) red[threadIdx.x >> 5] = v;
    __syncthreads();
    if (threadIdx.x < 32) {
        int r = red[threadIdx.x];
#pragma unroll
        for (int o = 16; o; o >>= 1) r += __shfl_down_sync(0xFFFFFFFFu, r, o);
        if (threadIdx.x == 0) g_bsum[blockIdx.x] = r;
    }
}

__global__ void scan_tops_kernel() {
    int lane = threadIdx.x;
    int v0 = (lane < NBLK) ? g_bsum[lane] : 0;
    int v1 = (lane + 32 < NBLK) ? g_bsum[lane + 32] : 0;
    int a = v0;
#pragma unroll
    for (int o = 1; o < 32; o <<= 1) {
        int t = __shfl_up_sync(0xFFFFFFFFu, a, o);
        if (lane >= o) a += t;
    }
    int tot0 = __shfl_sync(0xFFFFFFFFu, a, 31);
    int b = v1;
#pragma unroll
    for (int o = 1; o < 32; o <<= 1) {
        int t = __shfl_up_sync(0xFFFFFFFFu, b, o);
        if (lane >= o) b += t;
    }
    b += tot0;
    if (lane < NBLK) g_boff[lane] = a - v0;
    if (lane + 32 < NBLK) g_boff[lane + 32] = b - v1;
    if (lane == 31) g_rowptr[N_NODES] = (NBLK > 32) ? __shfl_sync(0xFFFFFFFFu, b, 31)
                                                    : tot0;
}

__global__ __launch_bounds__(SCAN_B) void scan_final_kernel() {
    __shared__ int warp_tot[32];
    int i = blockIdx.x * SCAN_B + threadIdx.x;
    int v = (i < N_NODES) ? g_deg[i] : 0;
    int lane = threadIdx.x & 31, w = threadIdx.x >> 5;
    int a = v;
#pragma unroll
    for (int o = 1; o < 32; o <<= 1) {
        int t = __shfl_up_sync(0xFFFFFFFFu, a, o);
        if (lane >= o) a += t;
    }
    if (lane == 31) warp_tot[w] = a;
    __syncthreads();
    if (threadIdx.x < 32) {
        int t = warp_tot[threadIdx.x];
        int s = t;
#pragma unroll
        for (int o = 1; o < 32; o <<= 1) {
            int u = __shfl_up_sync(0xFFFFFFFFu, s, o);
            if (threadIdx.x >= o) s += u;
        }
        warp_tot[threadIdx.x] = s - t;
    }
    __syncthreads();
    int excl = a - v + warp_tot[w] + g_boff[blockIdx.x];
    if (i < N_NODES) { g_rowptr[i] = excl; g_cursor[i] = excl; }
}

__global__ void scatter_kernel() {
    int i = blockIdx.x * blockDim.x + threadIdx.x;
    if (i >= ET) return;
    int pos = atomicAdd(&g_cursor[g_dst[i]], 1);
    g_csr_src[pos] = g_src[i];
}

// ---------------- split-fp16 tensor-core GEMM v2 ------------------------------
// Padded smem tiles (bank-conflict-free-ish), BK=32, 4x2 warp grid, two-phase
// fp32 staging (128x64) for fp16 mirror + fused attention logits.
template<int K, int NOUT, int BN>
__global__ __launch_bounds__(256)
void hgemm_kernel(const float* __restrict__ A,
                  const __half* __restrict__ Bh, const __half* __restrict__ Bl,
                  __half* __restrict__ Ch,
                  const float* __restrict__ att_s, const float* __restrict__ att_d,
                  float* __restrict__ AS, float* __restrict__ AD, int M) {
    constexpr int BM = 128, BK = 32;
    constexpr int WN = BN / 2;            // 64 (L1) or 32 (L2)
    constexpr int FN = WN / 16;           // 4 or 2
    constexpr int LDA = BK + 8;           // 40
    constexpr int LDB = BN + 8;           // 136 or 72
    constexpr int LDC = 68;
    constexpr int PHASES = BN / 64;       // 2 or 1
    constexpr int HEADS = NOUT / 64;

    extern __shared__ char smem[];
    half* sAh = (half*)smem;
    half* sAl = sAh + BM * LDA;
    half* sBh = sAl + BM * LDA;
    half* sBl = sBh + BK * LDB;
    float* Cs = (float*)smem;             // 128 x 64 staging (reused)

    int t = threadIdx.x, wid = t >> 5;
    int wr = wid & 3, wc = wid >> 2;      // 4 x 2 warp grid
    int warpM = wr * 32, warpN = wc * WN;
    int rowBase = blockIdx.y * BM, colBase = blockIdx.x * BN;

    wmma::fragment<wmma::accumulator, 16, 16, 16, float> acc[2][FN];
#pragma unroll
    for (int i = 0; i < 2; i++)
#pragma unroll
        for (int j = 0; j < FN; j++) wmma::fill_fragment(acc[i][j], 0.f);

    for (int kt = 0; kt < K; kt += BK) {
        // A tile: 128x32 fp32 -> split halves
        {
            int r = t >> 1, c = (t & 1) * 16;
            int gr = rowBase + r;
            float va[16];
#pragma unroll
            for (int i = 0; i < 16; i++) va[i] = 0.f;
            if (gr < M) {
#pragma unroll
                for (int q = 0; q < 4; q++) {
                    float4 v = *(const float4*)&A[(size_t)gr * K + kt + c + q * 4];
                    va[q * 4 + 0] = v.x; va[q * 4 + 1] = v.y;
                    va[q * 4 + 2] = v.z; va[q * 4 + 3] = v.w;
                }
            }
#pragma unroll
            for (int i = 0; i < 16; i++) {
                __half h = __float2half_rn(va[i]);
                sAh[r * LDA + c + i] = h;
                sAl[r * LDA + c + i] = __float2half_rn(va[i] - __half2float(h));
            }
        }
        // B tile: 32xBN halves (hi+lo)
#pragma unroll
        for (int u = 0; u < BN / 64; u++) {
            int idx = t + u * 256;
            int br = idx / (BN / 8), bc = (idx % (BN / 8)) * 8;
            *(uint4*)&sBh[br * LDB + bc] =
                *(const uint4*)&Bh[(size_t)(kt + br) * NOUT + colBase + bc];
            *(uint4*)&sBl[br * LDB + bc] =
                *(const uint4*)&Bl[(size_t)(kt + br) * NOUT + colBase + bc];
        }
        __syncthreads();
#pragma unroll
        for (int kf = 0; kf < 2; kf++) {
            wmma::fragment<wmma::matrix_a, 16, 16, 16, half, wmma::row_major> ah[2], al[2];
#pragma unroll
            for (int i = 0; i < 2; i++) {
                wmma::load_matrix_sync(ah[i], sAh + (warpM + i * 16) * LDA + kf * 16, LDA);
                wmma::load_matrix_sync(al[i], sAl + (warpM + i * 16) * LDA + kf * 16, LDA);
            }
#pragma unroll
            for (int j = 0; j < FN; j++) {
                wmma::fragment<wmma::matrix_b, 16, 16, 16, half, wmma::row_major> bh, bl;
                wmma::load_matrix_sync(bh, sBh + kf * 16 * LDB + warpN + j * 16, LDB);
                wmma::load_matrix_sync(bl, sBl + kf * 16 * LDB + warpN + j * 16, LDB);
#pragma unroll
                for (int i = 0; i < 2; i++) {
                    wmma::mma_sync(acc[i][j], ah[i], bh, acc[i][j]);
                    wmma::mma_sync(acc[i][j], al[i], bh, acc[i][j]);
                    wmma::mma_sync(acc[i][j], ah[i], bl, acc[i][j]);
                }
            }
        }
        __syncthreads();
    }

    // epilogue: per 64-col phase, stage fp32 -> fp16 mirror + logits
#pragma unroll
    for (int p = 0; p < PHASES; p++) {
        if (PHASES == 1 || wc == p) {
#pragma unroll
            for (int i = 0; i < 2; i++)
#pragma unroll
                for (int j = 0; j < FN; j++)
                    wmma::store_matrix_sync(
                        Cs + (warpM + i * 16) * LDC + (warpN - p * 64 + j * 16),
                        acc[i][j], LDC, wmma::mem_row_major);
        }
        __syncthreads();
        // mirror: 128 rows x 64 cols
        {
            int cr = t >> 1, cc = (t & 1) * 32;
            int gr = rowBase + cr;
            if (gr < M) {
#pragma unroll
                for (int q = 0; q < 32; q += 2) {
                    float x0 = Cs[cr * LDC + cc + q];
                    float x1 = Cs[cr * LDC + cc + q + 1];
                    *(__half2*)&Ch[(size_t)gr * NOUT + colBase + p * 64 + cc + q] =
                        __floats2half2_rn(x0, x1);
                }
            }
        }
        // logits for this head
        if (t < BM) {
            int n = rowBase + t;
            if (n < M) {
                int head = colBase / 64 + p;
                const float* Sv = att_s + head * 64;
                const float* Dv = att_d + head * 64;
                const float* row = Cs + t * LDC;
                float s = 0.f, d = 0.f;
#pragma unroll
                for (int c = 0; c < 64; c++) {
                    s += row[c] * Sv[c];
                    d += row[c] * Dv[c];
                }
                AS[n * HEADS + head] = s;
                AD[n * HEADS + head] = d;
            }
        }
        __syncthreads();
    }
}

// ---------------- per-node softmax (warp per node), writes alpha -------------
__global__ void softmax1_kernel() {
    int w = (blockIdx.x * blockDim.x + threadIdx.x) >> 5;
    int lane = threadIdx.x & 31;
    if (w >= N_NODES) return;
    int lo = g_rowptr[w], hi = g_rowptr[w + 1];
    float4 ad = *(const float4*)&g_ad1[w * 4];
    float m0 = -1e30f, m1 = -1e30f, m2 = -1e30f, m3 = -1e30f;
    float s0 = 0.f, s1 = 0.f, s2 = 0.f, s3 = 0.f;
    for (int k = lo + lane; k < hi; k += 32) {
        int s = g_csr_src[k];
        float4 as = *(const float4*)&g_as1[s * 4];
        float v0 = lrelu(as.x + ad.x), v1 = lrelu(as.y + ad.y);
        float v2 = lrelu(as.z + ad.z), v3 = lrelu(as.w + ad.w);
        if (v0 > m0) { s0 *= __expf(m0 - v0); m0 = v0; }  s0 += __expf(v0 - m0);
        if (v1 > m1) { s1 *= __expf(m1 - v1); m1 = v1; }  s1 += __expf(v1 - m1);
        if (v2 > m2) { s2 *= __expf(m2 - v2); m2 = v2; }  s2 += __expf(v2 - m2);
        if (v3 > m3) { s3 *= __expf(m3 - v3); m3 = v3; }  s3 += __expf(v3 - m3);
    }
#pragma unroll
    for (int off = 16; off; off >>= 1) {
        float mo, so, mn;
        mo = __shfl_xor_sync(0xFFFFFFFFu, m0, off); so = __shfl_xor_sync(0xFFFFFFFFu, s0, off);
        mn = fmaxf(m0, mo); s0 = s0 * __expf(m0 - mn) + so * __expf(mo - mn); m0 = mn;
        mo = __shfl_xor_sync(0xFFFFFFFFu, m1, off); so = __shfl_xor_sync(0xFFFFFFFFu, s1, off);
        mn = fmaxf(m1, mo); s1 = s1 * __expf(m1 - mn) + so * __expf(mo - mn); m1 = mn;
        mo = __shfl_xor_sync(0xFFFFFFFFu, m2, off); so = __shfl_xor_sync(0xFFFFFFFFu, s2, off);
        mn = fmaxf(m2, mo); s2 = s2 * __expf(m2 - mn) + so * __expf(mo - mn); m2 = mn;
        mo = __shfl_xor_sync(0xFFFFFFFFu, m3, off); so = __shfl_xor_sync(0xFFFFFFFFu, s3, off);
        mn = fmaxf(m3, mo); s3 = s3 * __expf(m3 - mn) + so * __expf(mo - mn); m3 = mn;
    }
    float i0 = 1.f / (s0 + EPS_DEN), i1 = 1.f / (s1 + EPS_DEN);
    float i2 = 1.f / (s2 + EPS_DEN), i3 = 1.f / (s3 + EPS_DEN);
    for (int k = lo + lane; k < hi; k += 32) {
        int s = g_csr_src[k];
        float4 as = *(const float4*)&g_as1[s * 4];
        float a0 = __expf(lrelu(as.x + ad.x) - m0) * i0;
        float a1 = __expf(lrelu(as.y + ad.y) - m1) * i1;
        float a2 = __expf(lrelu(as.z + ad.z) - m2) * i2;
        float a3 = __expf(lrelu(as.w + ad.w) - m3) * i3;
        *(float4*)&g_alpha1[k * 4] = make_float4(a0, a1, a2, a3);
    }
}

__global__ void softmax2_kernel() {
    int w = (blockIdx.x * blockDim.x + threadIdx.x) >> 5;
    int lane = threadIdx.x & 31;
    if (w >= N_NODES) return;
    int lo = g_rowptr[w], hi = g_rowptr[w + 1];
    float ad = g_ad2[w];
    float m = -1e30f, s = 0.f;
    for (int k = lo + lane; k < hi; k += 32) {
        float v = lrelu(g_as2[g_csr_src[k]] + ad);
        if (v > m) { s *= __expf(m - v); m = v; }
        s += __expf(v - m);
    }
#pragma unroll
    for (int off = 16; off; off >>= 1) {
        float mo = __shfl_xor_sync(0xFFFFFFFFu, m, off);
        float so = __shfl_xor_sync(0xFFFFFFFFu, s, off);
        float mn = fmaxf(m, mo);
        s = s * __expf(m - mn) + so * __expf(mo - mn);
        m = mn;
    }
    float inv = 1.f / (s + EPS_DEN);
    for (int k = lo + lane; k < hi; k += 32) {
        float v = lrelu(g_as2[g_csr_src[k]] + ad);
        g_alpha2[k] = __expf(v - m) * inv;
    }
}

// ---------------- aggregation (fp16 half2 gathers, 4-way unroll) --------------
__global__ __launch_bounds__(128)
void agg1_kernel(const float* __restrict__ b1) {
    int n = blockIdx.x;
    int c2 = threadIdx.x;
    int h = c2 >> 5;
    int lo = g_rowptr[n], hi = g_rowptr[n + 1];
    const __half2* H = (const __half2*)g_h1h;
    float ax = 0.f, ay = 0.f, bx = 0.f, by = 0.f;
    float cx = 0.f, cy = 0.f, dx = 0.f, dy = 0.f;
    int k = lo;
    for (; k + 3 < hi; k += 4) {
        int s0 = g_csr_src[k],     s1 = g_csr_src[k + 1];
        int s2 = g_csr_src[k + 2], s3 = g_csr_src[k + 3];
        float a0 = g_alpha1[k * 4 + h],       a1 = g_alpha1[(k + 1) * 4 + h];
        float a2 = g_alpha1[(k + 2) * 4 + h], a3 = g_alpha1[(k + 3) * 4 + h];
        float2 v0 = __half22float2(__ldg(&H[(size_t)s0 * 128 + c2]));
        float2 v1 = __half22float2(__ldg(&H[(size_t)s1 * 128 + c2]));
        float2 v2 = __half22float2(__ldg(&H[(size_t)s2 * 128 + c2]));
        float2 v3 = __half22float2(__ldg(&H[(size_t)s3 * 128 + c2]));
        ax += a0 * v0.x; ay += a0 * v0.y;
        bx += a1 * v1.x; by += a1 * v1.y;
        cx += a2 * v2.x; cy += a2 * v2.y;
        dx += a3 * v3.x; dy += a3 * v3.y;
    }
    for (; k < hi; k++) {
        int s0 = g_csr_src[k];
        float a0 = g_alpha1[k * 4 + h];
        float2 v0 = __half22float2(__ldg(&H[(size_t)s0 * 128 + c2]));
        ax += a0 * v0.x; ay += a0 * v0.y;
    }
    float vx = (ax + bx) + (cx + dx) + b1[2 * c2];
    float vy = (ay + by) + (cy + dy) + b1[2 * c2 + 1];
    float2 r;
    r.x = vx > 0.f ? vx : expm1f(vx);
    r.y = vy > 0.f ? vy : expm1f(vy);
    *(float2*)&g_x2[(size_t)n * HC1 + 2 * c2] = r;
}

__global__ __launch_bounds__(64)
void agg2_kernel(float* __restrict__ out, const float* __restrict__ b2) {
    int n = blockIdx.x * 2 + (threadIdx.x >> 5);
    if (n >= N_NODES) return;
    int c2 = threadIdx.x & 31;
    int lo = g_rowptr[n], hi = g_rowptr[n + 1];
    const __half2* H = (const __half2*)g_h2h;
    float ax = 0.f, ay = 0.f, bx = 0.f, by = 0.f;
    float cx = 0.f, cy = 0.f, dx = 0.f, dy = 0.f;
    int k = lo;
    for (; k + 3 < hi; k += 4) {
        int s0 = g_csr_src[k],     s1 = g_csr_src[k + 1];
        int s2 = g_csr_src[k + 2], s3 = g_csr_src[k + 3];
        float a0 = g_alpha2[k],     a1 = g_alpha2[k + 1];
        float a2 = g_alpha2[k + 2], a3 = g_alpha2[k + 3];
        float2 v0 = __half22float2(__ldg(&H[(size_t)s0 * 32 + c2]));
        float2 v1 = __half22float2(__ldg(&H[(size_t)s1 * 32 + c2]));
        float2 v2 = __half22float2(__ldg(&H[(size_t)s2 * 32 + c2]));
        float2 v3 = __half22float2(__ldg(&H[(size_t)s3 * 32 + c2]));
        ax += a0 * v0.x; ay += a0 * v0.y;
        bx += a1 * v1.x; by += a1 * v1.y;
        cx += a2 * v2.x; cy += a2 * v2.y;
        dx += a3 * v3.x; dy += a3 * v3.y;
    }
    for (; k < hi; k++) {
        int s0 = g_csr_src[k];
        float a0 = g_alpha2[k];
        float2 v0 = __half22float2(__ldg(&H[(size_t)s0 * 32 + c2]));
        ax += a0 * v0.x; ay += a0 * v0.y;
    }
    float2 r;
    r.x = (ax + bx) + (cx + dx) + b2[2 * c2];
    r.y = (ay + by) + (cy + dy) + b2[2 * c2 + 1];
    *(float2*)&out[(size_t)n * C2 + 2 * c2] = r;
}

// ---------------- launch ------------------------------------------------------
static inline int cdiv(long long a, int b) { return (int)((a + b - 1) / b); }

extern "C" void kernel_launch(void* const* d_in, const int* in_sizes, int n_in,
                              void* d_out, int out_size) {
    const float* x        = (const float*)d_in[0];
    const void*  ei       = d_in[1];
    const float* W1       = (const float*)d_in[2];
    const float* att_src1 = (const float*)d_in[3];
    const float* att_dst1 = (const float*)d_in[4];
    const float* b1       = (const float*)d_in[5];
    const float* W2       = (const float*)d_in[6];
    const float* att_src2 = (const float*)d_in[7];
    const float* att_dst2 = (const float*)d_in[8];
    const float* b2       = (const float*)d_in[9];
    float* out = (float*)d_out;

    float *x2, *as1, *ad1, *as2, *ad2;
    __half *h1h, *h2h, *w1h, *w1l, *w2h, *w2l;
    cudaGetSymbolAddress((void**)&x2, g_x2);
    cudaGetSymbolAddress((void**)&h1h, g_h1h);
    cudaGetSymbolAddress((void**)&h2h, g_h2h);
    cudaGetSymbolAddress((void**)&as1, g_as1);
    cudaGetSymbolAddress((void**)&ad1, g_ad1);
    cudaGetSymbolAddress((void**)&as2, g_as2);
    cudaGetSymbolAddress((void**)&ad2, g_ad2);
    cudaGetSymbolAddress((void**)&w1h, g_W1h);
    cudaGetSymbolAddress((void**)&w1l, g_W1l);
    cudaGetSymbolAddress((void**)&w2h, g_W2h);
    cudaGetSymbolAddress((void**)&w2l, g_W2l);

    const int T = 256;
    // smem: tiles = 2*128*40*2 + 2*32*(BN+8)*2 ; staging = 128*68*4
    const int TILES1 = 2 * 128 * 40 * 2 + 2 * 32 * 136 * 2;   // 37888
    const int TILES2 = 2 * 128 * 40 * 2 + 2 * 32 * 72 * 2;    // 29696
    const int STAGE  = 128 * 68 * 4;                          // 34816
    const int SMEM1 = TILES1 > STAGE ? TILES1 : STAGE;        // 37888
    const int SMEM2 = TILES2 > STAGE ? TILES2 : STAGE;        // 34816

    cudaFuncSetAttribute(hgemm_kernel<F_IN, HC1, 128>,
                         cudaFuncAttributeMaxDynamicSharedMemorySize, SMEM1);
    cudaFuncSetAttribute(hgemm_kernel<HC1, C2, 64>,
                         cudaFuncAttributeMaxDynamicSharedMemorySize, SMEM2);

    prep_kernel<<<cdiv(F_IN * HC1 + HC1 * C2, T), T>>>(W1, W2);     // #1
    detzero_kernel<<<cdiv(N_NODES, T), T>>>((const int*)ei);        // #2
    edges_kernel<<<cdiv(ET, T), T>>>(ei);                           // #3
    // #4: hgemm1 — profiled next round
    {
        dim3 grid(HC1 / 128, cdiv(N_NODES, 128));
        hgemm_kernel<F_IN, HC1, 128><<<grid, T, SMEM1>>>(
            x, w1h, w1l, h1h, att_src1, att_dst1, as1, ad1, N_NODES);
    }
    scan_partial_kernel<<<NBLK, SCAN_B>>>();
    scan_tops_kernel<<<1, 32>>>();
    scan_final_kernel<<<NBLK, SCAN_B>>>();
    scatter_kernel<<<cdiv(ET, T), T>>>();
    softmax1_kernel<<<cdiv((long long)N_NODES * 32, T), T>>>();
    agg1_kernel<<<N_NODES, 128>>>(b1);
    {
        dim3 grid(1, cdiv(N_NODES, 128));
        hgemm_kernel<HC1, C2, 64><<<grid, T, SMEM2>>>(
            x2, w2h, w2l, h2h, att_src2, att_dst2, as2, ad2, N_NODES);
    }
    softmax2_kernel<<<cdiv((long long)N_NODES * 32, T), T>>>();
    agg2_kernel<<<cdiv(N_NODES, 2), 64>>>(out, b2);
}

// round 13
// speedup vs baseline: 1.1986x; 1.0459x over previous
#include <cuda_runtime.h>
#include <cuda_fp16.h>
#include <mma.h>
#include <math.h>
using namespace nvcuda;

#define N_NODES 50000
#define E_EDGES 800000
#define ET      (E_EDGES + N_NODES)   // 850000 edges incl. self loops
#define F_IN    128
#define H1      4
#define C1      64
#define HC1     256
#define C2      64
#define NEG_SLOPE 0.2f
#define EPS_DEN 1e-16f
#define SCAN_B  1024
#define NBLK    ((N_NODES + SCAN_B - 1) / SCAN_B)   // 49

// ---------------- scratch (device globals; 16B-aligned) ----------------------
__device__ __align__(16) __half g_h1h[N_NODES * HC1];   // layer1 features (fp16)
__device__ __align__(16) float  g_x2 [N_NODES * HC1];   // elu(agg1+b1), fp32
__device__ __align__(16) __half g_h2h[N_NODES * C2];    // layer2 features (fp16)
__device__ __align__(16) __half g_W1h[F_IN * HC1];      // split weights
__device__ __align__(16) __half g_W1l[F_IN * HC1];
__device__ __align__(16) __half g_W2h[HC1 * C2];
__device__ __align__(16) __half g_W2l[HC1 * C2];
__device__ __align__(16) float  g_as1[N_NODES * H1];
__device__ __align__(16) float  g_ad1[N_NODES * H1];
__device__ __align__(16) float  g_as2[N_NODES];
__device__ __align__(16) float  g_ad2[N_NODES];
__device__ __align__(16) float  g_alpha1[ET * H1];
__device__ __align__(16) float  g_alpha2[ET];
__device__ __align__(16) int    g_src[ET];
__device__ __align__(16) int    g_dst[ET];
__device__ __align__(16) int    g_csr_src[ET];
__device__ __align__(16) int    g_rowptr[N_NODES + 1];
__device__ __align__(16) int    g_cursor[N_NODES];
__device__ __align__(16) int    g_deg[N_NODES];
__device__ __align__(16) int    g_bsum[NBLK];
__device__ __align__(16) int    g_boff[NBLK];
__device__ int g_is64;

// ---------------- helpers ----------------------------------------------------
__device__ __forceinline__ int clampN(int v) {
    return v < 0 ? 0 : (v >= N_NODES ? N_NODES - 1 : v);
}
__device__ __forceinline__ float lrelu(float v) {
    return v > 0.f ? v : NEG_SLOPE * v;
}

// ---------------- prep: split weights into fp16 hi/lo -------------------------
__global__ void prep_kernel(const float* __restrict__ W1, const float* __restrict__ W2) {
    int i = blockIdx.x * blockDim.x + threadIdx.x;
    if (i < F_IN * HC1) {
        float v = W1[i];
        __half h = __float2half_rn(v);
        g_W1h[i] = h;
        g_W1l[i] = __float2half_rn(v - __half2float(h));
    }
    int j = i - F_IN * HC1;
    if (j >= 0 && j < HC1 * C2) {
        float v = W2[j];
        __half h = __float2half_rn(v);
        g_W2h[j] = h;
        g_W2l[j] = __float2half_rn(v - __half2float(h));
    }
}

// ---------------- detect dtype + zero degree ----------------------------------
__global__ void detzero_kernel(const int* __restrict__ ei32) {
    int i = blockIdx.x * blockDim.x + threadIdx.x;
    if (i < N_NODES) g_deg[i] = 0;
    if (blockIdx.x == 0 && threadIdx.x < 32) {
        int lane = threadIdx.x;
        int v = ei32[2 * lane + 1] | ei32[2 * (lane + 32) + 1] |
                ei32[2 * (lane + 64) + 1] | ei32[2 * (lane + 96) + 1];
#pragma unroll
        for (int o = 16; o; o >>= 1) v |= __shfl_xor_sync(0xFFFFFFFFu, v, o);
        if (lane == 0) g_is64 = (v == 0) ? 1 : 0;
    }
}

__global__ void edges_kernel(const void* __restrict__ ei) {
    int i = blockIdx.x * blockDim.x + threadIdx.x;
    if (i >= ET) return;
    int s, d;
    if (i < E_EDGES) {
        if (g_is64) {
            const long long* p = (const long long*)ei;
            s = (int)p[i];  d = (int)p[E_EDGES + i];
        } else {
            const int* p = (const int*)ei;
            s = p[i];  d = p[E_EDGES + i];
        }
        s = clampN(s); d = clampN(d);
    } else {
        s = d = i - E_EDGES;
    }
    g_src[i] = s;
    g_dst[i] = d;
    atomicAdd(&g_deg[d], 1);
}

// ---------------- 3-phase parallel scan of g_deg -> g_rowptr ------------------
__global__ __launch_bounds__(SCAN_B) void scan_partial_kernel() {
    __shared__ int red[32];
    int i = blockIdx.x * SCAN_B + threadIdx.x;
    int v = (i < N_NODES) ? g_deg[i] : 0;
#pragma unroll
    for (int o = 16; o; o >>= 1) v += __shfl_down_sync(0xFFFFFFFFu, v, o);
    if ((threadIdx.x & 31) == 0) red[threadIdx.x >> 5] = v;
    __syncthreads();
    if (threadIdx.x < 32) {
        int r = red[threadIdx.x];
#pragma unroll
        for (int o = 16; o; o >>= 1) r += __shfl_down_sync(0xFFFFFFFFu, r, o);
        if (threadIdx.x == 0) g_bsum[blockIdx.x] = r;
    }
}

__global__ void scan_tops_kernel() {
    int lane = threadIdx.x;
    int v0 = (lane < NBLK) ? g_bsum[lane] : 0;
    int v1 = (lane + 32 < NBLK) ? g_bsum[lane + 32] : 0;
    int a = v0;
#pragma unroll
    for (int o = 1; o < 32; o <<= 1) {
        int t = __shfl_up_sync(0xFFFFFFFFu, a, o);
        if (lane >= o) a += t;
    }
    int tot0 = __shfl_sync(0xFFFFFFFFu, a, 31);
    int b = v1;
#pragma unroll
    for (int o = 1; o < 32; o <<= 1) {
        int t = __shfl_up_sync(0xFFFFFFFFu, b, o);
        if (lane >= o) b += t;
    }
    b += tot0;
    if (lane < NBLK) g_boff[lane] = a - v0;
    if (lane + 32 < NBLK) g_boff[lane + 32] = b - v1;
    if (lane == 31) g_rowptr[N_NODES] = (NBLK > 32) ? __shfl_sync(0xFFFFFFFFu, b, 31)
                                                    : tot0;
}

__global__ __launch_bounds__(SCAN_B) void scan_final_kernel() {
    __shared__ int warp_tot[32];
    int i = blockIdx.x * SCAN_B + threadIdx.x;
    int v = (i < N_NODES) ? g_deg[i] : 0;
    int lane = threadIdx.x & 31, w = threadIdx.x >> 5;
    int a = v;
#pragma unroll
    for (int o = 1; o < 32; o <<= 1) {
        int t = __shfl_up_sync(0xFFFFFFFFu, a, o);
        if (lane >= o) a += t;
    }
    if (lane == 31) warp_tot[w] = a;
    __syncthreads();
    if (threadIdx.x < 32) {
        int t = warp_tot[threadIdx.x];
        int s = t;
#pragma unroll
        for (int o = 1; o < 32; o <<= 1) {
            int u = __shfl_up_sync(0xFFFFFFFFu, s, o);
            if (threadIdx.x >= o) s += u;
        }
        warp_tot[threadIdx.x] = s - t;
    }
    __syncthreads();
    int excl = a - v + warp_tot[w] + g_boff[blockIdx.x];
    if (i < N_NODES) { g_rowptr[i] = excl; g_cursor[i] = excl; }
}

__global__ void scatter_kernel() {
    int i = blockIdx.x * blockDim.x + threadIdx.x;
    if (i >= ET) return;
    int pos = atomicAdd(&g_cursor[g_dst[i]], 1);
    g_csr_src[pos] = g_src[i];
}

// ---------------- split-fp16 tensor-core GEMM v3 ------------------------------
// Block tile 128x64, 4x2 warp grid, warp tile 32x32, BK=32, padded smem.
// __launch_bounds__(256,2) caps regs at 128 -> 2 blocks/SM (16 warps).
template<int K, int NOUT>
__global__ __launch_bounds__(256, 2)
void hgemm_kernel(const float* __restrict__ A,
                  const __half* __restrict__ Bh, const __half* __restrict__ Bl,
                  __half* __restrict__ Ch,
                  const float* __restrict__ att_s, const float* __restrict__ att_d,
                  float* __restrict__ AS, float* __restrict__ AD, int M) {
    constexpr int BM = 128, BN = 64, BK = 32;
    constexpr int LDA = BK + 8;           // 40
    constexpr int LDB = BN + 8;           // 72
    constexpr int LDC = 68;
    constexpr int HEADS = NOUT / 64;

    extern __shared__ char smem[];
    half* sAh = (half*)smem;
    half* sAl = sAh + BM * LDA;
    half* sBh = sAl + BM * LDA;
    half* sBl = sBh + BK * LDB;
    float* Cs = (float*)smem;             // 128 x 68 staging (reused)

    int t = threadIdx.x, wid = t >> 5;
    int wr = wid & 3, wc = wid >> 2;      // 4 x 2 warp grid
    int warpM = wr * 32, warpN = wc * 32;
    int rowBase = blockIdx.y * BM, colBase = blockIdx.x * BN;

    wmma::fragment<wmma::accumulator, 16, 16, 16, float> acc[2][2];
#pragma unroll
    for (int i = 0; i < 2; i++)
#pragma unroll
        for (int j = 0; j < 2; j++) wmma::fill_fragment(acc[i][j], 0.f);

    for (int kt = 0; kt < K; kt += BK) {
        // A tile: 128x32 fp32 -> split halves
        {
            int r = t >> 1, c = (t & 1) * 16;
            int gr = rowBase + r;
            float va[16];
#pragma unroll
            for (int i = 0; i < 16; i++) va[i] = 0.f;
            if (gr < M) {
#pragma unroll
                for (int q = 0; q < 4; q++) {
                    float4 v = *(const float4*)&A[(size_t)gr * K + kt + c + q * 4];
                    va[q * 4 + 0] = v.x; va[q * 4 + 1] = v.y;
                    va[q * 4 + 2] = v.z; va[q * 4 + 3] = v.w;
                }
            }
#pragma unroll
            for (int i = 0; i < 16; i++) {
                __half h = __float2half_rn(va[i]);
                sAh[r * LDA + c + i] = h;
                sAl[r * LDA + c + i] = __float2half_rn(va[i] - __half2float(h));
            }
        }
        // B tile: 32x64 halves (hi+lo) -> 256 uint4 each, 1 per thread
        {
            int br = t >> 3, bc = (t & 7) * 8;
            *(uint4*)&sBh[br * LDB + bc] =
                *(const uint4*)&Bh[(size_t)(kt + br) * NOUT + colBase + bc];
            *(uint4*)&sBl[br * LDB + bc] =
                *(const uint4*)&Bl[(size_t)(kt + br) * NOUT + colBase + bc];
        }
        __syncthreads();
#pragma unroll
        for (int kf = 0; kf < 2; kf++) {
            wmma::fragment<wmma::matrix_a, 16, 16, 16, half, wmma::row_major> ah[2], al[2];
#pragma unroll
            for (int i = 0; i < 2; i++) {
                wmma::load_matrix_sync(ah[i], sAh + (warpM + i * 16) * LDA + kf * 16, LDA);
                wmma::load_matrix_sync(al[i], sAl + (warpM + i * 16) * LDA + kf * 16, LDA);
            }
#pragma unroll
            for (int j = 0; j < 2; j++) {
                wmma::fragment<wmma::matrix_b, 16, 16, 16, half, wmma::row_major> bh, bl;
                wmma::load_matrix_sync(bh, sBh + kf * 16 * LDB + warpN + j * 16, LDB);
                wmma::load_matrix_sync(bl, sBl + kf * 16 * LDB + warpN + j * 16, LDB);
#pragma unroll
                for (int i = 0; i < 2; i++) {
                    wmma::mma_sync(acc[i][j], ah[i], bh, acc[i][j]);
                    wmma::mma_sync(acc[i][j], al[i], bh, acc[i][j]);
                    wmma::mma_sync(acc[i][j], ah[i], bl, acc[i][j]);
                }
            }
        }
        __syncthreads();
    }

    // epilogue: stage fp32 -> fp16 mirror + fused logits (direct stores)
#pragma unroll
    for (int i = 0; i < 2; i++)
#pragma unroll
        for (int j = 0; j < 2; j++)
            wmma::store_matrix_sync(Cs + (warpM + i * 16) * LDC + warpN + j * 16,
                                    acc[i][j], LDC, wmma::mem_row_major);
    __syncthreads();
    // mirror: 128 rows x 64 cols
    {
        int cr = t >> 1, cc = (t & 1) * 32;
        int gr = rowBase + cr;
        if (gr < M) {
#pragma unroll
            for (int q = 0; q < 32; q += 2) {
                float x0 = Cs[cr * LDC + cc + q];
                float x1 = Cs[cr * LDC + cc + q + 1];
                *(__half2*)&Ch[(size_t)gr * NOUT + colBase + cc + q] =
                    __floats2half2_rn(x0, x1);
            }
        }
    }
    // logits for this head
    if (t < BM) {
        int n = rowBase + t;
        if (n < M) {
            int head = colBase / 64;
            const float* Sv = att_s + head * 64;
            const float* Dv = att_d + head * 64;
            const float* row = Cs + t * LDC;
            float s = 0.f, d = 0.f;
#pragma unroll
            for (int c = 0; c < 64; c++) {
                s += row[c] * Sv[c];
                d += row[c] * Dv[c];
            }
            AS[n * HEADS + head] = s;
            AD[n * HEADS + head] = d;
        }
    }
}

// ---------------- per-node softmax (warp per node), writes alpha -------------
__global__ void softmax1_kernel() {
    int w = (blockIdx.x * blockDim.x + threadIdx.x) >> 5;
    int lane = threadIdx.x & 31;
    if (w >= N_NODES) return;
    int lo = g_rowptr[w], hi = g_rowptr[w + 1];
    float4 ad = *(const float4*)&g_ad1[w * 4];
    float m0 = -1e30f, m1 = -1e30f, m2 = -1e30f, m3 = -1e30f;
    float s0 = 0.f, s1 = 0.f, s2 = 0.f, s3 = 0.f;
    for (int k = lo + lane; k < hi; k += 32) {
        int s = g_csr_src[k];
        float4 as = *(const float4*)&g_as1[s * 4];
        float v0 = lrelu(as.x + ad.x), v1 = lrelu(as.y + ad.y);
        float v2 = lrelu(as.z + ad.z), v3 = lrelu(as.w + ad.w);
        if (v0 > m0) { s0 *= __expf(m0 - v0); m0 = v0; }  s0 += __expf(v0 - m0);
        if (v1 > m1) { s1 *= __expf(m1 - v1); m1 = v1; }  s1 += __expf(v1 - m1);
        if (v2 > m2) { s2 *= __expf(m2 - v2); m2 = v2; }  s2 += __expf(v2 - m2);
        if (v3 > m3) { s3 *= __expf(m3 - v3); m3 = v3; }  s3 += __expf(v3 - m3);
    }
#pragma unroll
    for (int off = 16; off; off >>= 1) {
        float mo, so, mn;
        mo = __shfl_xor_sync(0xFFFFFFFFu, m0, off); so = __shfl_xor_sync(0xFFFFFFFFu, s0, off);
        mn = fmaxf(m0, mo); s0 = s0 * __expf(m0 - mn) + so * __expf(mo - mn); m0 = mn;
        mo = __shfl_xor_sync(0xFFFFFFFFu, m1, off); so = __shfl_xor_sync(0xFFFFFFFFu, s1, off);
        mn = fmaxf(m1, mo); s1 = s1 * __expf(m1 - mn) + so * __expf(mo - mn); m1 = mn;
        mo = __shfl_xor_sync(0xFFFFFFFFu, m2, off); so = __shfl_xor_sync(0xFFFFFFFFu, s2, off);
        mn = fmaxf(m2, mo); s2 = s2 * __expf(m2 - mn) + so * __expf(mo - mn); m2 = mn;
        mo = __shfl_xor_sync(0xFFFFFFFFu, m3, off); so = __shfl_xor_sync(0xFFFFFFFFu, s3, off);
        mn = fmaxf(m3, mo); s3 = s3 * __expf(m3 - mn) + so * __expf(mo - mn); m3 = mn;
    }
    float i0 = 1.f / (s0 + EPS_DEN), i1 = 1.f / (s1 + EPS_DEN);
    float i2 = 1.f / (s2 + EPS_DEN), i3 = 1.f / (s3 + EPS_DEN);
    for (int k = lo + lane; k < hi; k += 32) {
        int s = g_csr_src[k];
        float4 as = *(const float4*)&g_as1[s * 4];
        float a0 = __expf(lrelu(as.x + ad.x) - m0) * i0;
        float a1 = __expf(lrelu(as.y + ad.y) - m1) * i1;
        float a2 = __expf(lrelu(as.z + ad.z) - m2) * i2;
        float a3 = __expf(lrelu(as.w + ad.w) - m3) * i3;
        *(float4*)&g_alpha1[k * 4] = make_float4(a0, a1, a2, a3);
    }
}

__global__ void softmax2_kernel() {
    int w = (blockIdx.x * blockDim.x + threadIdx.x) >> 5;
    int lane = threadIdx.x & 31;
    if (w >= N_NODES) return;
    int lo = g_rowptr[w], hi = g_rowptr[w + 1];
    float ad = g_ad2[w];
    float m = -1e30f, s = 0.f;
    for (int k = lo + lane; k < hi; k += 32) {
        float v = lrelu(g_as2[g_csr_src[k]] + ad);
        if (v > m) { s *= __expf(m - v); m = v; }
        s += __expf(v - m);
    }
#pragma unroll
    for (int off = 16; off; off >>= 1) {
        float mo = __shfl_xor_sync(0xFFFFFFFFu, m, off);
        float so = __shfl_xor_sync(0xFFFFFFFFu, s, off);
        float mn = fmaxf(m, mo);
        s = s * __expf(m - mn) + so * __expf(mo - mn);
        m = mn;
    }
    float inv = 1.f / (s + EPS_DEN);
    for (int k = lo + lane; k < hi; k += 32) {
        float v = lrelu(g_as2[g_csr_src[k]] + ad);
        g_alpha2[k] = __expf(v - m) * inv;
    }
}

// ---------------- aggregation (fp16 half2 gathers, 4-way unroll) --------------
__global__ __launch_bounds__(128)
void agg1_kernel(const float* __restrict__ b1) {
    int n = blockIdx.x;
    int c2 = threadIdx.x;
    int h = c2 >> 5;
    int lo = g_rowptr[n], hi = g_rowptr[n + 1];
    const __half2* H = (const __half2*)g_h1h;
    float ax = 0.f, ay = 0.f, bx = 0.f, by = 0.f;
    float cx = 0.f, cy = 0.f, dx = 0.f, dy = 0.f;
    int k = lo;
    for (; k + 3 < hi; k += 4) {
        int s0 = g_csr_src[k],     s1 = g_csr_src[k + 1];
        int s2 = g_csr_src[k + 2], s3 = g_csr_src[k + 3];
        float a0 = g_alpha1[k * 4 + h],       a1 = g_alpha1[(k + 1) * 4 + h];
        float a2 = g_alpha1[(k + 2) * 4 + h], a3 = g_alpha1[(k + 3) * 4 + h];
        float2 v0 = __half22float2(__ldg(&H[(size_t)s0 * 128 + c2]));
        float2 v1 = __half22float2(__ldg(&H[(size_t)s1 * 128 + c2]));
        float2 v2 = __half22float2(__ldg(&H[(size_t)s2 * 128 + c2]));
        float2 v3 = __half22float2(__ldg(&H[(size_t)s3 * 128 + c2]));
        ax += a0 * v0.x; ay += a0 * v0.y;
        bx += a1 * v1.x; by += a1 * v1.y;
        cx += a2 * v2.x; cy += a2 * v2.y;
        dx += a3 * v3.x; dy += a3 * v3.y;
    }
    for (; k < hi; k++) {
        int s0 = g_csr_src[k];
        float a0 = g_alpha1[k * 4 + h];
        float2 v0 = __half22float2(__ldg(&H[(size_t)s0 * 128 + c2]));
        ax += a0 * v0.x; ay += a0 * v0.y;
    }
    float vx = (ax + bx) + (cx + dx) + b1[2 * c2];
    float vy = (ay + by) + (cy + dy) + b1[2 * c2 + 1];
    float2 r;
    r.x = vx > 0.f ? vx : expm1f(vx);
    r.y = vy > 0.f ? vy : expm1f(vy);
    *(float2*)&g_x2[(size_t)n * HC1 + 2 * c2] = r;
}

__global__ __launch_bounds__(64)
void agg2_kernel(float* __restrict__ out, const float* __restrict__ b2) {
    int n = blockIdx.x * 2 + (threadIdx.x >> 5);
    if (n >= N_NODES) return;
    int c2 = threadIdx.x & 31;
    int lo = g_rowptr[n], hi = g_rowptr[n + 1];
    const __half2* H = (const __half2*)g_h2h;
    float ax = 0.f, ay = 0.f, bx = 0.f, by = 0.f;
    float cx = 0.f, cy = 0.f, dx = 0.f, dy = 0.f;
    int k = lo;
    for (; k + 3 < hi; k += 4) {
        int s0 = g_csr_src[k],     s1 = g_csr_src[k + 1];
        int s2 = g_csr_src[k + 2], s3 = g_csr_src[k + 3];
        float a0 = g_alpha2[k],     a1 = g_alpha2[k + 1];
        float a2 = g_alpha2[k + 2], a3 = g_alpha2[k + 3];
        float2 v0 = __half22float2(__ldg(&H[(size_t)s0 * 32 + c2]));
        float2 v1 = __half22float2(__ldg(&H[(size_t)s1 * 32 + c2]));
        float2 v2 = __half22float2(__ldg(&H[(size_t)s2 * 32 + c2]));
        float2 v3 = __half22float2(__ldg(&H[(size_t)s3 * 32 + c2]));
        ax += a0 * v0.x; ay += a0 * v0.y;
        bx += a1 * v1.x; by += a1 * v1.y;
        cx += a2 * v2.x; cy += a2 * v2.y;
        dx += a3 * v3.x; dy += a3 * v3.y;
    }
    for (; k < hi; k++) {
        int s0 = g_csr_src[k];
        float a0 = g_alpha2[k];
        float2 v0 = __half22float2(__ldg(&H[(size_t)s0 * 32 + c2]));
        ax += a0 * v0.x; ay += a0 * v0.y;
    }
    float2 r;
    r.x = (ax + bx) + (cx + dx) + b2[2 * c2];
    r.y = (ay + by) + (cy + dy) + b2[2 * c2 + 1];
    *(float2*)&out[(size_t)n * C2 + 2 * c2] = r;
}

// ---------------- launch ------------------------------------------------------
static inline int cdiv(long long a, int b) { return (int)((a + b - 1) / b); }

extern "C" void kernel_launch(void* const* d_in, const int* in_sizes, int n_in,
                              void* d_out, int out_size) {
    const float* x        = (const float*)d_in[0];
    const void*  ei       = d_in[1];
    const float* W1       = (const float*)d_in[2];
    const float* att_src1 = (const float*)d_in[3];
    const float* att_dst1 = (const float*)d_in[4];
    const float* b1       = (const float*)d_in[5];
    const float* W2       = (const float*)d_in[6];
    const float* att_src2 = (const float*)d_in[7];
    const float* att_dst2 = (const float*)d_in[8];
    const float* b2       = (const float*)d_in[9];
    float* out = (float*)d_out;

    float *x2, *as1, *ad1, *as2, *ad2;
    __half *h1h, *h2h, *w1h, *w1l, *w2h, *w2l;
    cudaGetSymbolAddress((void**)&x2, g_x2);
    cudaGetSymbolAddress((void**)&h1h, g_h1h);
    cudaGetSymbolAddress((void**)&h2h, g_h2h);
    cudaGetSymbolAddress((void**)&as1, g_as1);
    cudaGetSymbolAddress((void**)&ad1, g_ad1);
    cudaGetSymbolAddress((void**)&as2, g_as2);
    cudaGetSymbolAddress((void**)&ad2, g_ad2);
    cudaGetSymbolAddress((void**)&w1h, g_W1h);
    cudaGetSymbolAddress((void**)&w1l, g_W1l);
    cudaGetSymbolAddress((void**)&w2h, g_W2h);
    cudaGetSymbolAddress((void**)&w2l, g_W2l);

    const int T = 256;
    // smem: tiles = 2*128*40*2 + 2*32*72*2 = 29696 ; staging = 128*68*4 = 34816
    const int SMEM = 128 * 68 * 4;

    cudaFuncSetAttribute(hgemm_kernel<F_IN, HC1>,
                         cudaFuncAttributeMaxDynamicSharedMemorySize, SMEM);
    cudaFuncSetAttribute(hgemm_kernel<HC1, C2>,
                         cudaFuncAttributeMaxDynamicSharedMemorySize, SMEM);

    prep_kernel<<<cdiv(F_IN * HC1 + HC1 * C2, T), T>>>(W1, W2);     // #1
    detzero_kernel<<<cdiv(N_NODES, T), T>>>((const int*)ei);        // #2
    edges_kernel<<<cdiv(ET, T), T>>>(ei);                           // #3
    // #4: hgemm1 — profiled next round
    {
        dim3 grid(HC1 / 64, cdiv(N_NODES, 128));
        hgemm_kernel<F_IN, HC1><<<grid, T, SMEM>>>(
            x, w1h, w1l, h1h, att_src1, att_dst1, as1, ad1, N_NODES);
    }
    scan_partial_kernel<<<NBLK, SCAN_B>>>();
    scan_tops_kernel<<<1, 32>>>();
    scan_final_kernel<<<NBLK, SCAN_B>>>();
    scatter_kernel<<<cdiv(ET, T), T>>>();
    softmax1_kernel<<<cdiv((long long)N_NODES * 32, T), T>>>();
    agg1_kernel<<<N_NODES, 128>>>(b1);
    {
        dim3 grid(C2 / 64, cdiv(N_NODES, 128));
        hgemm_kernel<HC1, C2><<<grid, T, SMEM>>>(
            x2, w2h, w2l, h2h, att_src2, att_dst2, as2, ad2, N_NODES);
    }
    softmax2_kernel<<<cdiv((long long)N_NODES * 32, T), T>>>();
    agg2_kernel<<<cdiv(N_NODES, 2), 64>>>(out, b2);
}

// round 14
// speedup vs baseline: 1.2185x; 1.0166x over previous
#include <cuda_runtime.h>
#include <cuda_fp16.h>
#include <cuda_pipeline.h>
#include <mma.h>
#include <math.h>
using namespace nvcuda;

#define N_NODES 50000
#define E_EDGES 800000
#define ET      (E_EDGES + N_NODES)   // 850000 edges incl. self loops
#define F_IN    128
#define H1      4
#define C1      64
#define HC1     256
#define C2      64
#define NEG_SLOPE 0.2f
#define EPS_DEN 1e-16f
#define SCAN_B  1024
#define NBLK    ((N_NODES + SCAN_B - 1) / SCAN_B)   // 49

// ---------------- scratch (device globals; 16B-aligned) ----------------------
__device__ __align__(16) __half g_xh [N_NODES * F_IN];  // x split hi/lo
__device__ __align__(16) __half g_xl [N_NODES * F_IN];
__device__ __align__(16) __half g_h1h[N_NODES * HC1];   // layer1 features (fp16)
__device__ __align__(16) __half g_x2h[N_NODES * HC1];   // elu(agg1+b1) split hi/lo
__device__ __align__(16) __half g_x2l[N_NODES * HC1];
__device__ __align__(16) __half g_h2h[N_NODES * C2];    // layer2 features (fp16)
__device__ __align__(16) __half g_W1h[F_IN * HC1];      // split weights
__device__ __align__(16) __half g_W1l[F_IN * HC1];
__device__ __align__(16) __half g_W2h[HC1 * C2];
__device__ __align__(16) __half g_W2l[HC1 * C2];
__device__ __align__(16) float  g_as1[N_NODES * H1];
__device__ __align__(16) float  g_ad1[N_NODES * H1];
__device__ __align__(16) float  g_as2[N_NODES];
__device__ __align__(16) float  g_ad2[N_NODES];
__device__ __align__(16) float  g_alpha1[ET * H1];
__device__ __align__(16) float  g_alpha2[ET];
__device__ __align__(16) int    g_src[ET];
__device__ __align__(16) int    g_dst[ET];
__device__ __align__(16) int    g_csr_src[ET];
__device__ __align__(16) int    g_rowptr[N_NODES + 1];
__device__ __align__(16) int    g_cursor[N_NODES];
__device__ __align__(16) int    g_deg[N_NODES];
__device__ __align__(16) int    g_bsum[NBLK];
__device__ __align__(16) int    g_boff[NBLK];
__device__ int g_is64;

// ---------------- helpers ----------------------------------------------------
__device__ __forceinline__ int clampN(int v) {
    return v < 0 ? 0 : (v >= N_NODES ? N_NODES - 1 : v);
}
__device__ __forceinline__ float lrelu(float v) {
    return v > 0.f ? v : NEG_SLOPE * v;
}

// ---------------- prep: split weights + x into fp16 hi/lo ---------------------
__global__ void prep_kernel(const float* __restrict__ W1, const float* __restrict__ W2) {
    int i = blockIdx.x * blockDim.x + threadIdx.x;
    if (i < F_IN * HC1) {
        float v = W1[i];
        __half h = __float2half_rn(v);
        g_W1h[i] = h;
        g_W1l[i] = __float2half_rn(v - __half2float(h));
    }
    int j = i - F_IN * HC1;
    if (j >= 0 && j < HC1 * C2) {
        float v = W2[j];
        __half h = __float2half_rn(v);
        g_W2h[j] = h;
        g_W2l[j] = __float2half_rn(v - __half2float(h));
    }
}

__global__ void xsplit_kernel(const float* __restrict__ x) {
    int i = blockIdx.x * blockDim.x + threadIdx.x;
    if (i >= N_NODES * F_IN / 2) return;
    float2 v = *(const float2*)&x[2 * i];
    __half h0 = __float2half_rn(v.x), h1 = __float2half_rn(v.y);
    ((__half2*)g_xh)[i] = __halves2half2(h0, h1);
    ((__half2*)g_xl)[i] = __floats2half2_rn(v.x - __half2float(h0),
                                            v.y - __half2float(h1));
}

// ---------------- detect dtype + zero degree ----------------------------------
__global__ void detzero_kernel(const int* __restrict__ ei32) {
    int i = blockIdx.x * blockDim.x + threadIdx.x;
    if (i < N_NODES) g_deg[i] = 0;
    if (blockIdx.x == 0 && threadIdx.x < 32) {
        int lane = threadIdx.x;
        int v = ei32[2 * lane + 1] | ei32[2 * (lane + 32) + 1] |
                ei32[2 * (lane + 64) + 1] | ei32[2 * (lane + 96) + 1];
#pragma unroll
        for (int o = 16; o; o >>= 1) v |= __shfl_xor_sync(0xFFFFFFFFu, v, o);
        if (lane == 0) g_is64 = (v == 0) ? 1 : 0;
    }
}

__global__ void edges_kernel(const void* __restrict__ ei) {
    int i = blockIdx.x * blockDim.x + threadIdx.x;
    if (i >= ET) return;
    int s, d;
    if (i < E_EDGES) {
        if (g_is64) {
            const long long* p = (const long long*)ei;
            s = (int)p[i];  d = (int)p[E_EDGES + i];
        } else {
            const int* p = (const int*)ei;
            s = p[i];  d = p[E_EDGES + i];
        }
        s = clampN(s); d = clampN(d);
    } else {
        s = d = i - E_EDGES;
    }
    g_src[i] = s;
    g_dst[i] = d;
    atomicAdd(&g_deg[d], 1);
}

// ---------------- 3-phase parallel scan of g_deg -> g_rowptr ------------------
__global__ __launch_bounds__(SCAN_B) void scan_partial_kernel() {
    __shared__ int red[32];
    int i = blockIdx.x * SCAN_B + threadIdx.x;
    int v = (i < N_NODES) ? g_deg[i] : 0;
#pragma unroll
    for (int o = 16; o; o >>= 1) v += __shfl_down_sync(0xFFFFFFFFu, v, o);
    if ((threadIdx.x & 31) == 0) red[threadIdx.x >> 5] = v;
    __syncthreads();
    if (threadIdx.x < 32) {
        int r = red[threadIdx.x];
#pragma unroll
        for (int o = 16; o; o >>= 1) r += __shfl_down_sync(0xFFFFFFFFu, r, o);
        if (threadIdx.x == 0) g_bsum[blockIdx.x] = r;
    }
}

__global__ void scan_tops_kernel() {
    int lane = threadIdx.x;
    int v0 = (lane < NBLK) ? g_bsum[lane] : 0;
    int v1 = (lane + 32 < NBLK) ? g_bsum[lane + 32] : 0;
    int a = v0;
#pragma unroll
    for (int o = 1; o < 32; o <<= 1) {
        int t = __shfl_up_sync(0xFFFFFFFFu, a, o);
        if (lane >= o) a += t;
    }
    int tot0 = __shfl_sync(0xFFFFFFFFu, a, 31);
    int b = v1;
#pragma unroll
    for (int o = 1; o < 32; o <<= 1) {
        int t = __shfl_up_sync(0xFFFFFFFFu, b, o);
        if (lane >= o) b += t;
    }
    b += tot0;
    if (lane < NBLK) g_boff[lane] = a - v0;
    if (lane + 32 < NBLK) g_boff[lane + 32] = b - v1;
    if (lane == 31) g_rowptr[N_NODES] = (NBLK > 32) ? __shfl_sync(0xFFFFFFFFu, b, 31)
                                                    : tot0;
}

__global__ __launch_bounds__(SCAN_B) void scan_final_kernel() {
    __shared__ int warp_tot[32];
    int i = blockIdx.x * SCAN_B + threadIdx.x;
    int v = (i < N_NODES) ? g_deg[i] : 0;
    int lane = threadIdx.x & 31, w = threadIdx.x >> 5;
    int a = v;
#pragma unroll
    for (int o = 1; o < 32; o <<= 1) {
        int t = __shfl_up_sync(0xFFFFFFFFu, a, o);
        if (lane >= o) a += t;
    }
    if (lane == 31) warp_tot[w] = a;
    __syncthreads();
    if (threadIdx.x < 32) {
        int t = warp_tot[threadIdx.x];
        int s = t;
#pragma unroll
        for (int o = 1; o < 32; o <<= 1) {
            int u = __shfl_up_sync(0xFFFFFFFFu, s, o);
            if (threadIdx.x >= o) s += u;
        }
        warp_tot[threadIdx.x] = s - t;
    }
    __syncthreads();
    int excl = a - v + warp_tot[w] + g_boff[blockIdx.x];
    if (i < N_NODES) { g_rowptr[i] = excl; g_cursor[i] = excl; }
}

__global__ void scatter_kernel() {
    int i = blockIdx.x * blockDim.x + threadIdx.x;
    if (i >= ET) return;
    int pos = atomicAdd(&g_cursor[g_dst[i]], 1);
    g_csr_src[pos] = g_src[i];
}

// ---------------- split-fp16 tensor-core GEMM v4 ------------------------------
// A pre-split fp16 hi/lo in global; cp.async double-buffered tiles; block tile
// 128x64, 4x2 warps, warp tile 32x32, BK=32. Same 3-MMA split math as before.
template<int K, int NOUT>
__global__ __launch_bounds__(256, 2)
void hgemm_kernel(const __half* __restrict__ Ah, const __half* __restrict__ Al,
                  const __half* __restrict__ Bh, const __half* __restrict__ Bl,
                  __half* __restrict__ Ch,
                  const float* __restrict__ att_s, const float* __restrict__ att_d,
                  float* __restrict__ AS, float* __restrict__ AD, int M) {
    constexpr int BM = 128, BN = 64, BK = 32;
    constexpr int LDA = BK + 8;           // 40 halves (80B, 16B-multiple)
    constexpr int LDB = BN + 8;           // 72 halves (144B)
    constexpr int LDC = 68;
    constexpr int ASZ = BM * LDA;         // 5120 halves
    constexpr int BSZ = BK * LDB;         // 2304 halves
    constexpr int NK  = K / BK;
    constexpr int HEADS = NOUT / 64;

    extern __shared__ char smem[];
    half* base = (half*)smem;
    // [sAh0 sAh1 sAl0 sAl1 sBh0 sBh1 sBl0 sBl1]
    float* Cs = (float*)smem;             // reused for epilogue staging

    int t = threadIdx.x, wid = t >> 5;
    int wr = wid & 3, wc = wid >> 2;      // 4 x 2 warp grid
    int warpM = wr * 32, warpN = wc * 32;
    int rowBase = blockIdx.y * BM, colBase = blockIdx.x * BN;

    auto load_tiles = [&](int kt, int buf) {
        half* sAh = base + buf * ASZ;
        half* sAl = base + 2 * ASZ + buf * ASZ;
        half* sBh = base + 4 * ASZ + buf * BSZ;
        half* sBl = base + 4 * ASZ + 2 * BSZ + buf * BSZ;
        // A: 128 rows x 32 halves = 4 x16B chunks/row, 512 chunks -> 2/thread
#pragma unroll
        for (int i = 0; i < 2; i++) {
            int c = t * 2 + i;
            int r = c >> 2, q = (c & 3) * 8;
            int gr = rowBase + r;
            if (gr < M) {
                __pipeline_memcpy_async(sAh + r * LDA + q,
                                        Ah + (size_t)gr * K + kt + q, 16);
                __pipeline_memcpy_async(sAl + r * LDA + q,
                                        Al + (size_t)gr * K + kt + q, 16);
            }
        }
        // B: 32 rows x 64 halves = 8 x16B chunks/row, 256 chunks -> 1/thread
        {
            int r = t >> 3, q = (t & 7) * 8;
            __pipeline_memcpy_async(sBh + r * LDB + q,
                                    Bh + (size_t)(kt + r) * NOUT + colBase + q, 16);
            __pipeline_memcpy_async(sBl + r * LDB + q,
                                    Bl + (size_t)(kt + r) * NOUT + colBase + q, 16);
        }
        __pipeline_commit();
    };

    wmma::fragment<wmma::accumulator, 16, 16, 16, float> acc[2][2];
#pragma unroll
    for (int i = 0; i < 2; i++)
#pragma unroll
        for (int j = 0; j < 2; j++) wmma::fill_fragment(acc[i][j], 0.f);

    load_tiles(0, 0);
    for (int k = 0; k < NK; k++) {
        if (k + 1 < NK) load_tiles((k + 1) * BK, (k + 1) & 1);
        __pipeline_wait_prior((k + 1 < NK) ? 1 : 0);
        __syncthreads();
        int buf = k & 1;
        half* sAh = base + buf * ASZ;
        half* sAl = base + 2 * ASZ + buf * ASZ;
        half* sBh = base + 4 * ASZ + buf * BSZ;
        half* sBl = base + 4 * ASZ + 2 * BSZ + buf * BSZ;
#pragma unroll
        for (int kf = 0; kf < 2; kf++) {
            wmma::fragment<wmma::matrix_a, 16, 16, 16, half, wmma::row_major> ah[2], al[2];
#pragma unroll
            for (int i = 0; i < 2; i++) {
                wmma::load_matrix_sync(ah[i], sAh + (warpM + i * 16) * LDA + kf * 16, LDA);
                wmma::load_matrix_sync(al[i], sAl + (warpM + i * 16) * LDA + kf * 16, LDA);
            }
#pragma unroll
            for (int j = 0; j < 2; j++) {
                wmma::fragment<wmma::matrix_b, 16, 16, 16, half, wmma::row_major> bh, bl;
                wmma::load_matrix_sync(bh, sBh + kf * 16 * LDB + warpN + j * 16, LDB);
                wmma::load_matrix_sync(bl, sBl + kf * 16 * LDB + warpN + j * 16, LDB);
#pragma unroll
                for (int i = 0; i < 2; i++) {
                    wmma::mma_sync(acc[i][j], ah[i], bh, acc[i][j]);
                    wmma::mma_sync(acc[i][j], al[i], bh, acc[i][j]);
                    wmma::mma_sync(acc[i][j], ah[i], bl, acc[i][j]);
                }
            }
        }
        __syncthreads();
    }

    // epilogue: stage fp32 -> fp16 mirror + fused logits (direct stores)
#pragma unroll
    for (int i = 0; i < 2; i++)
#pragma unroll
        for (int j = 0; j < 2; j++)
            wmma::store_matrix_sync(Cs + (warpM + i * 16) * LDC + warpN + j * 16,
                                    acc[i][j], LDC, wmma::mem_row_major);
    __syncthreads();
    {
        int cr = t >> 1, cc = (t & 1) * 32;
        int gr = rowBase + cr;
        if (gr < M) {
#pragma unroll
            for (int q = 0; q < 32; q += 2) {
                float x0 = Cs[cr * LDC + cc + q];
                float x1 = Cs[cr * LDC + cc + q + 1];
                *(__half2*)&Ch[(size_t)gr * NOUT + colBase + cc + q] =
                    __floats2half2_rn(x0, x1);
            }
        }
    }
    if (t < BM) {
        int n = rowBase + t;
        if (n < M) {
            int head = colBase / 64;
            const float* Sv = att_s + head * 64;
            const float* Dv = att_d + head * 64;
            const float* row = Cs + t * LDC;
            float s = 0.f, d = 0.f;
#pragma unroll
            for (int c = 0; c < 64; c++) {
                s += row[c] * Sv[c];
                d += row[c] * Dv[c];
            }
            AS[n * HEADS + head] = s;
            AD[n * HEADS + head] = d;
        }
    }
}

// ---------------- per-node softmax (warp per node), writes alpha -------------
__global__ void softmax1_kernel() {
    int w = (blockIdx.x * blockDim.x + threadIdx.x) >> 5;
    int lane = threadIdx.x & 31;
    if (w >= N_NODES) return;
    int lo = g_rowptr[w], hi = g_rowptr[w + 1];
    float4 ad = *(const float4*)&g_ad1[w * 4];
    float m0 = -1e30f, m1 = -1e30f, m2 = -1e30f, m3 = -1e30f;
    float s0 = 0.f, s1 = 0.f, s2 = 0.f, s3 = 0.f;
    for (int k = lo + lane; k < hi; k += 32) {
        int s = g_csr_src[k];
        float4 as = *(const float4*)&g_as1[s * 4];
        float v0 = lrelu(as.x + ad.x), v1 = lrelu(as.y + ad.y);
        float v2 = lrelu(as.z + ad.z), v3 = lrelu(as.w + ad.w);
        if (v0 > m0) { s0 *= __expf(m0 - v0); m0 = v0; }  s0 += __expf(v0 - m0);
        if (v1 > m1) { s1 *= __expf(m1 - v1); m1 = v1; }  s1 += __expf(v1 - m1);
        if (v2 > m2) { s2 *= __expf(m2 - v2); m2 = v2; }  s2 += __expf(v2 - m2);
        if (v3 > m3) { s3 *= __expf(m3 - v3); m3 = v3; }  s3 += __expf(v3 - m3);
    }
#pragma unroll
    for (int off = 16; off; off >>= 1) {
        float mo, so, mn;
        mo = __shfl_xor_sync(0xFFFFFFFFu, m0, off); so = __shfl_xor_sync(0xFFFFFFFFu, s0, off);
        mn = fmaxf(m0, mo); s0 = s0 * __expf(m0 - mn) + so * __expf(mo - mn); m0 = mn;
        mo = __shfl_xor_sync(0xFFFFFFFFu, m1, off); so = __shfl_xor_sync(0xFFFFFFFFu, s1, off);
        mn = fmaxf(m1, mo); s1 = s1 * __expf(m1 - mn) + so * __expf(mo - mn); m1 = mn;
        mo = __shfl_xor_sync(0xFFFFFFFFu, m2, off); so = __shfl_xor_sync(0xFFFFFFFFu, s2, off);
        mn = fmaxf(m2, mo); s2 = s2 * __expf(m2 - mn) + so * __expf(mo - mn); m2 = mn;
        mo = __shfl_xor_sync(0xFFFFFFFFu, m3, off); so = __shfl_xor_sync(0xFFFFFFFFu, s3, off);
        mn = fmaxf(m3, mo); s3 = s3 * __expf(m3 - mn) + so * __expf(mo - mn); m3 = mn;
    }
    float i0 = 1.f / (s0 + EPS_DEN), i1 = 1.f / (s1 + EPS_DEN);
    float i2 = 1.f / (s2 + EPS_DEN), i3 = 1.f / (s3 + EPS_DEN);
    for (int k = lo + lane; k < hi; k += 32) {
        int s = g_csr_src[k];
        float4 as = *(const float4*)&g_as1[s * 4];
        float a0 = __expf(lrelu(as.x + ad.x) - m0) * i0;
        float a1 = __expf(lrelu(as.y + ad.y) - m1) * i1;
        float a2 = __expf(lrelu(as.z + ad.z) - m2) * i2;
        float a3 = __expf(lrelu(as.w + ad.w) - m3) * i3;
        *(float4*)&g_alpha1[k * 4] = make_float4(a0, a1, a2, a3);
    }
}

__global__ void softmax2_kernel() {
    int w = (blockIdx.x * blockDim.x + threadIdx.x) >> 5;
    int lane = threadIdx.x & 31;
    if (w >= N_NODES) return;
    int lo = g_rowptr[w], hi = g_rowptr[w + 1];
    float ad = g_ad2[w];
    float m = -1e30f, s = 0.f;
    for (int k = lo + lane; k < hi; k += 32) {
        float v = lrelu(g_as2[g_csr_src[k]] + ad);
        if (v > m) { s *= __expf(m - v); m = v; }
        s += __expf(v - m);
    }
#pragma unroll
    for (int off = 16; off; off >>= 1) {
        float mo = __shfl_xor_sync(0xFFFFFFFFu, m, off);
        float so = __shfl_xor_sync(0xFFFFFFFFu, s, off);
        float mn = fmaxf(m, mo);
        s = s * __expf(m - mn) + so * __expf(mo - mn);
        m = mn;
    }
    float inv = 1.f / (s + EPS_DEN);
    for (int k = lo + lane; k < hi; k += 32) {
        float v = lrelu(g_as2[g_csr_src[k]] + ad);
        g_alpha2[k] = __expf(v - m) * inv;
    }
}

// ---------------- aggregation (fp16 half2 gathers, 4-way unroll) --------------
// agg1 writes x2 split hi/lo fp16 directly (bit-identical to fp32->split later)
__global__ __launch_bounds__(128)
void agg1_kernel(const float* __restrict__ b1) {
    int n = blockIdx.x;
    int c2 = threadIdx.x;
    int h = c2 >> 5;
    int lo = g_rowptr[n], hi = g_rowptr[n + 1];
    const __half2* H = (const __half2*)g_h1h;
    float ax = 0.f, ay = 0.f, bx = 0.f, by = 0.f;
    float cx = 0.f, cy = 0.f, dx = 0.f, dy = 0.f;
    int k = lo;
    for (; k + 3 < hi; k += 4) {
        int s0 = g_csr_src[k],     s1 = g_csr_src[k + 1];
        int s2 = g_csr_src[k + 2], s3 = g_csr_src[k + 3];
        float a0 = g_alpha1[k * 4 + h],       a1 = g_alpha1[(k + 1) * 4 + h];
        float a2 = g_alpha1[(k + 2) * 4 + h], a3 = g_alpha1[(k + 3) * 4 + h];
        float2 v0 = __half22float2(__ldg(&H[(size_t)s0 * 128 + c2]));
        float2 v1 = __half22float2(__ldg(&H[(size_t)s1 * 128 + c2]));
        float2 v2 = __half22float2(__ldg(&H[(size_t)s2 * 128 + c2]));
        float2 v3 = __half22float2(__ldg(&H[(size_t)s3 * 128 + c2]));
        ax += a0 * v0.x; ay += a0 * v0.y;
        bx += a1 * v1.x; by += a1 * v1.y;
        cx += a2 * v2.x; cy += a2 * v2.y;
        dx += a3 * v3.x; dy += a3 * v3.y;
    }
    for (; k < hi; k++) {
        int s0 = g_csr_src[k];
        float a0 = g_alpha1[k * 4 + h];
        float2 v0 = __half22float2(__ldg(&H[(size_t)s0 * 128 + c2]));
        ax += a0 * v0.x; ay += a0 * v0.y;
    }
    float vx = (ax + bx) + (cx + dx) + b1[2 * c2];
    float vy = (ay + by) + (cy + dy) + b1[2 * c2 + 1];
    vx = vx > 0.f ? vx : expm1f(vx);
    vy = vy > 0.f ? vy : expm1f(vy);
    __half hx = __float2half_rn(vx), hy = __float2half_rn(vy);
    ((__half2*)g_x2h)[((size_t)n * HC1 + 2 * c2) / 2] = __halves2half2(hx, hy);
    ((__half2*)g_x2l)[((size_t)n * HC1 + 2 * c2) / 2] =
        __floats2half2_rn(vx - __half2float(hx), vy - __half2float(hy));
}

__global__ __launch_bounds__(64)
void agg2_kernel(float* __restrict__ out, const float* __restrict__ b2) {
    int n = blockIdx.x * 2 + (threadIdx.x >> 5);
    if (n >= N_NODES) return;
    int c2 = threadIdx.x & 31;
    int lo = g_rowptr[n], hi = g_rowptr[n + 1];
    const __half2* H = (const __half2*)g_h2h;
    float ax = 0.f, ay = 0.f, bx = 0.f, by = 0.f;
    float cx = 0.f, cy = 0.f, dx = 0.f, dy = 0.f;
    int k = lo;
    for (; k + 3 < hi; k += 4) {
        int s0 = g_csr_src[k],     s1 = g_csr_src[k + 1];
        int s2 = g_csr_src[k + 2], s3 = g_csr_src[k + 3];
        float a0 = g_alpha2[k],     a1 = g_alpha2[k + 1];
        float a2 = g_alpha2[k + 2], a3 = g_alpha2[k + 3];
        float2 v0 = __half22float2(__ldg(&H[(size_t)s0 * 32 + c2]));
        float2 v1 = __half22float2(__ldg(&H[(size_t)s1 * 32 + c2]));
        float2 v2 = __half22float2(__ldg(&H[(size_t)s2 * 32 + c2]));
        float2 v3 = __half22float2(__ldg(&H[(size_t)s3 * 32 + c2]));
        ax += a0 * v0.x; ay += a0 * v0.y;
        bx += a1 * v1.x; by += a1 * v1.y;
        cx += a2 * v2.x; cy += a2 * v2.y;
        dx += a3 * v3.x; dy += a3 * v3.y;
    }
    for (; k < hi; k++) {
        int s0 = g_csr_src[k];
        float a0 = g_alpha2[k];
        float2 v0 = __half22float2(__ldg(&H[(size_t)s0 * 32 + c2]));
        ax += a0 * v0.x; ay += a0 * v0.y;
    }
    float2 r;
    r.x = (ax + bx) + (cx + dx) + b2[2 * c2];
    r.y = (ay + by) + (cy + dy) + b2[2 * c2 + 1];
    *(float2*)&out[(size_t)n * C2 + 2 * c2] = r;
}

// ---------------- launch ------------------------------------------------------
static inline int cdiv(long long a, int b) { return (int)((a + b - 1) / b); }

extern "C" void kernel_launch(void* const* d_in, const int* in_sizes, int n_in,
                              void* d_out, int out_size) {
    const float* x        = (const float*)d_in[0];
    const void*  ei       = d_in[1];
    const float* W1       = (const float*)d_in[2];
    const float* att_src1 = (const float*)d_in[3];
    const float* att_dst1 = (const float*)d_in[4];
    const float* b1       = (const float*)d_in[5];
    const float* W2       = (const float*)d_in[6];
    const float* att_src2 = (const float*)d_in[7];
    const float* att_dst2 = (const float*)d_in[8];
    const float* b2       = (const float*)d_in[9];
    float* out = (float*)d_out;

    float *as1, *ad1, *as2, *ad2;
    __half *xh, *xl, *x2h, *x2l, *h1h, *h2h, *w1h, *w1l, *w2h, *w2l;
    cudaGetSymbolAddress((void**)&xh,  g_xh);
    cudaGetSymbolAddress((void**)&xl,  g_xl);
    cudaGetSymbolAddress((void**)&x2h, g_x2h);
    cudaGetSymbolAddress((void**)&x2l, g_x2l);
    cudaGetSymbolAddress((void**)&h1h, g_h1h);
    cudaGetSymbolAddress((void**)&h2h, g_h2h);
    cudaGetSymbolAddress((void**)&as1, g_as1);
    cudaGetSymbolAddress((void**)&ad1, g_ad1);
    cudaGetSymbolAddress((void**)&as2, g_as2);
    cudaGetSymbolAddress((void**)&ad2, g_ad2);
    cudaGetSymbolAddress((void**)&w1h, g_W1h);
    cudaGetSymbolAddress((void**)&w1l, g_W1l);
    cudaGetSymbolAddress((void**)&w2h, g_W2h);
    cudaGetSymbolAddress((void**)&w2l, g_W2l);

    const int T = 256;
    // smem: tiles = 4*5120*2B + 4*2304*2B = 40960+18432 = 59392 ; staging 34816
    const int SMEM = 59392;

    cudaFuncSetAttribute(hgemm_kernel<F_IN, HC1>,
                         cudaFuncAttributeMaxDynamicSharedMemorySize, SMEM);
    cudaFuncSetAttribute(hgemm_kernel<HC1, C2>,
                         cudaFuncAttributeMaxDynamicSharedMemorySize, SMEM);

    prep_kernel<<<cdiv(F_IN * HC1 + HC1 * C2, T), T>>>(W1, W2);     // #1
    detzero_kernel<<<cdiv(N_NODES, T), T>>>((const int*)ei);        // #2
    xsplit_kernel<<<cdiv((long long)N_NODES * F_IN / 2, T), T>>>(x);// #3
    // #4: hgemm1 — profiled next round
    {
        dim3 grid(HC1 / 64, cdiv(N_NODES, 128));
        hgemm_kernel<F_IN, HC1><<<grid, T, SMEM>>>(
            xh, xl, w1h, w1l, h1h, att_src1, att_dst1, as1, ad1, N_NODES);
    }
    edges_kernel<<<cdiv(ET, T), T>>>(ei);
    scan_partial_kernel<<<NBLK, SCAN_B>>>();
    scan_tops_kernel<<<1, 32>>>();
    scan_final_kernel<<<NBLK, SCAN_B>>>();
    scatter_kernel<<<cdiv(ET, T), T>>>();
    softmax1_kernel<<<cdiv((long long)N_NODES * 32, T), T>>>();
    agg1_kernel<<<N_NODES, 128>>>(b1);
    {
        dim3 grid(C2 / 64, cdiv(N_NODES, 128));
        hgemm_kernel<HC1, C2><<<grid, T, SMEM>>>(
            x2h, x2l, w2h, w2l, h2h, att_src2, att_dst2, as2, ad2, N_NODES);
    }
    softmax2_kernel<<<cdiv((long long)N_NODES * 32, T), T>>>();
    agg2_kernel<<<cdiv(N_NODES, 2), 64>>>(out, b2);
}

// round 15
// speedup vs baseline: 1.3390x; 1.0989x over previous
#include <cuda_runtime.h>
#include <cuda_fp16.h>
#include <cuda_pipeline.h>
#include <mma.h>
#include <math.h>
using namespace nvcuda;

#define N_NODES 50000
#define E_EDGES 800000
#define ET      (E_EDGES + N_NODES)   // 850000 edges incl. self loops
#define F_IN    128
#define H1      4
#define C1      64
#define HC1     256
#define C2      64
#define NEG_SLOPE 0.2f
#define EPS_DEN 1e-16f
#define SCAN_B  1024
#define NBLK    ((N_NODES + SCAN_B - 1) / SCAN_B)   // 49

// ---------------- scratch (device globals; 16B-aligned) ----------------------
__device__ __align__(16) __half g_xh [N_NODES * F_IN];  // x fp16
__device__ __align__(16) __half g_h1h[N_NODES * HC1];   // layer1 features (fp16)
__device__ __align__(16) __half g_x2h[N_NODES * HC1];   // elu(agg1+b1) fp16
__device__ __align__(16) __half g_h2h[N_NODES * C2];    // layer2 features (fp16)
__device__ __align__(16) __half g_W1h[F_IN * HC1];      // split weights (hi/lo)
__device__ __align__(16) __half g_W1l[F_IN * HC1];
__device__ __align__(16) __half g_W2h[HC1 * C2];
__device__ __align__(16) __half g_W2l[HC1 * C2];
__device__ __align__(16) float  g_as1[N_NODES * H1];
__device__ __align__(16) float  g_ad1[N_NODES * H1];
__device__ __align__(16) float  g_as2[N_NODES];
__device__ __align__(16) float  g_ad2[N_NODES];
__device__ __align__(16) float  g_alpha1[ET * H1];
__device__ __align__(16) float  g_alpha2[ET];
__device__ __align__(16) int    g_src[ET];
__device__ __align__(16) int    g_dst[ET];
__device__ __align__(16) int    g_csr_src[ET];
__device__ __align__(16) int    g_rowptr[N_NODES + 1];
__device__ __align__(16) int    g_cursor[N_NODES];
__device__ __align__(16) int    g_deg[N_NODES];
__device__ __align__(16) int    g_bsum[NBLK];
__device__ __align__(16) int    g_boff[NBLK];
__device__ int g_is64;

// ---------------- helpers ----------------------------------------------------
__device__ __forceinline__ int clampN(int v) {
    return v < 0 ? 0 : (v >= N_NODES ? N_NODES - 1 : v);
}
__device__ __forceinline__ float lrelu(float v) {
    return v > 0.f ? v : NEG_SLOPE * v;
}

// ---------------- prep: split weights (hi/lo), x -> fp16 ----------------------
__global__ void prep_kernel(const float* __restrict__ W1, const float* __restrict__ W2) {
    int i = blockIdx.x * blockDim.x + threadIdx.x;
    if (i < F_IN * HC1) {
        float v = W1[i];
        __half h = __float2half_rn(v);
        g_W1h[i] = h;
        g_W1l[i] = __float2half_rn(v - __half2float(h));
    }
    int j = i - F_IN * HC1;
    if (j >= 0 && j < HC1 * C2) {
        float v = W2[j];
        __half h = __float2half_rn(v);
        g_W2h[j] = h;
        g_W2l[j] = __float2half_rn(v - __half2float(h));
    }
}

__global__ void xsplit_kernel(const float* __restrict__ x) {
    int i = blockIdx.x * blockDim.x + threadIdx.x;
    if (i >= N_NODES * F_IN / 2) return;
    float2 v = *(const float2*)&x[2 * i];
    ((__half2*)g_xh)[i] = __floats2half2_rn(v.x, v.y);
}

// ---------------- detect dtype + zero degree ----------------------------------
__global__ void detzero_kernel(const int* __restrict__ ei32) {
    int i = blockIdx.x * blockDim.x + threadIdx.x;
    if (i < N_NODES) g_deg[i] = 0;
    if (blockIdx.x == 0 && threadIdx.x < 32) {
        int lane = threadIdx.x;
        int v = ei32[2 * lane + 1] | ei32[2 * (lane + 32) + 1] |
                ei32[2 * (lane + 64) + 1] | ei32[2 * (lane + 96) + 1];
#pragma unroll
        for (int o = 16; o; o >>= 1) v |= __shfl_xor_sync(0xFFFFFFFFu, v, o);
        if (lane == 0) g_is64 = (v == 0) ? 1 : 0;
    }
}

__global__ void edges_kernel(const void* __restrict__ ei) {
    int i = blockIdx.x * blockDim.x + threadIdx.x;
    if (i >= ET) return;
    int s, d;
    if (i < E_EDGES) {
        if (g_is64) {
            const long long* p = (const long long*)ei;
            s = (int)p[i];  d = (int)p[E_EDGES + i];
        } else {
            const int* p = (const int*)ei;
            s = p[i];  d = p[E_EDGES + i];
        }
        s = clampN(s); d = clampN(d);
    } else {
        s = d = i - E_EDGES;
    }
    g_src[i] = s;
    g_dst[i] = d;
    atomicAdd(&g_deg[d], 1);
}

// ---------------- 3-phase parallel scan of g_deg -> g_rowptr ------------------
__global__ __launch_bounds__(SCAN_B) void scan_partial_kernel() {
    __shared__ int red[32];
    int i = blockIdx.x * SCAN_B + threadIdx.x;
    int v = (i < N_NODES) ? g_deg[i] : 0;
#pragma unroll
    for (int o = 16; o; o >>= 1) v += __shfl_down_sync(0xFFFFFFFFu, v, o);
    if ((threadIdx.x & 31) == 0) red[threadIdx.x >> 5] = v;
    __syncthreads();
    if (threadIdx.x < 32) {
        int r = red[threadIdx.x];
#pragma unroll
        for (int o = 16; o; o >>= 1) r += __shfl_down_sync(0xFFFFFFFFu, r, o);
        if (threadIdx.x == 0) g_bsum[blockIdx.x] = r;
    }
}

__global__ void scan_tops_kernel() {
    int lane = threadIdx.x;
    int v0 = (lane < NBLK) ? g_bsum[lane] : 0;
    int v1 = (lane + 32 < NBLK) ? g_bsum[lane + 32] : 0;
    int a = v0;
#pragma unroll
    for (int o = 1; o < 32; o <<= 1) {
        int t = __shfl_up_sync(0xFFFFFFFFu, a, o);
        if (lane >= o) a += t;
    }
    int tot0 = __shfl_sync(0xFFFFFFFFu, a, 31);
    int b = v1;
#pragma unroll
    for (int o = 1; o < 32; o <<= 1) {
        int t = __shfl_up_sync(0xFFFFFFFFu, b, o);
        if (lane >= o) b += t;
    }
    b += tot0;
    if (lane < NBLK) g_boff[lane] = a - v0;
    if (lane + 32 < NBLK) g_boff[lane + 32] = b - v1;
    if (lane == 31) g_rowptr[N_NODES] = (NBLK > 32) ? __shfl_sync(0xFFFFFFFFu, b, 31)
                                                    : tot0;
}

__global__ __launch_bounds__(SCAN_B) void scan_final_kernel() {
    __shared__ int warp_tot[32];
    int i = blockIdx.x * SCAN_B + threadIdx.x;
    int v = (i < N_NODES) ? g_deg[i] : 0;
    int lane = threadIdx.x & 31, w = threadIdx.x >> 5;
    int a = v;
#pragma unroll
    for (int o = 1; o < 32; o <<= 1) {
        int t = __shfl_up_sync(0xFFFFFFFFu, a, o);
        if (lane >= o) a += t;
    }
    if (lane == 31) warp_tot[w] = a;
    __syncthreads();
    if (threadIdx.x < 32) {
        int t = warp_tot[threadIdx.x];
        int s = t;
#pragma unroll
        for (int o = 1; o < 32; o <<= 1) {
            int u = __shfl_up_sync(0xFFFFFFFFu, s, o);
            if (threadIdx.x >= o) s += u;
        }
        warp_tot[threadIdx.x] = s - t;
    }
    __syncthreads();
    int excl = a - v + warp_tot[w] + g_boff[blockIdx.x];
    if (i < N_NODES) { g_rowptr[i] = excl; g_cursor[i] = excl; }
}

__global__ void scatter_kernel() {
    int i = blockIdx.x * blockDim.x + threadIdx.x;
    if (i >= ET) return;
    int pos = atomicAdd(&g_cursor[g_dst[i]], 1);
    g_csr_src[pos] = g_src[i];
}

// ---------------- fp16-A x split-B tensor-core GEMM ---------------------------
// C = A_fp16 @ (Bh + Bl) : 2 MMAs per tile pair. cp.async double-buffered.
// Block tile 128x64, 4x2 warps, warp tile 32x32, BK=32.
template<int K, int NOUT>
__global__ __launch_bounds__(256, 3)
void hgemm_kernel(const __half* __restrict__ Ah,
                  const __half* __restrict__ Bh, const __half* __restrict__ Bl,
                  __half* __restrict__ Ch,
                  const float* __restrict__ att_s, const float* __restrict__ att_d,
                  float* __restrict__ AS, float* __restrict__ AD, int M) {
    constexpr int BM = 128, BN = 64, BK = 32;
    constexpr int LDA = BK + 8;           // 40 halves
    constexpr int LDB = BN + 8;           // 72 halves
    constexpr int LDC = 68;
    constexpr int ASZ = BM * LDA;         // 5120 halves
    constexpr int BSZ = BK * LDB;         // 2304 halves
    constexpr int NK  = K / BK;
    constexpr int HEADS = NOUT / 64;

    extern __shared__ char smem[];
    half* base = (half*)smem;
    // layout: [sA0 sA1 sBh0 sBh1 sBl0 sBl1]
    float* Cs = (float*)smem;             // reused for epilogue staging

    int t = threadIdx.x, wid = t >> 5;
    int wr = wid & 3, wc = wid >> 2;      // 4 x 2 warp grid
    int warpM = wr * 32, warpN = wc * 32;
    int rowBase = blockIdx.y * BM, colBase = blockIdx.x * BN;

    auto load_tiles = [&](int kt, int buf) {
        half* sA  = base + buf * ASZ;
        half* sBh = base + 2 * ASZ + buf * BSZ;
        half* sBl = base + 2 * ASZ + 2 * BSZ + buf * BSZ;
        // A: 128 rows x 32 halves = 4 x16B chunks/row, 512 chunks -> 2/thread
#pragma unroll
        for (int i = 0; i < 2; i++) {
            int c = t * 2 + i;
            int r = c >> 2, q = (c & 3) * 8;
            int gr = rowBase + r;
            if (gr < M)
                __pipeline_memcpy_async(sA + r * LDA + q,
                                        Ah + (size_t)gr * K + kt + q, 16);
        }
        // B: 32 rows x 64 halves = 8 x16B chunks/row, 256 chunks -> 1/thread
        {
            int r = t >> 3, q = (t & 7) * 8;
            __pipeline_memcpy_async(sBh + r * LDB + q,
                                    Bh + (size_t)(kt + r) * NOUT + colBase + q, 16);
            __pipeline_memcpy_async(sBl + r * LDB + q,
                                    Bl + (size_t)(kt + r) * NOUT + colBase + q, 16);
        }
        __pipeline_commit();
    };

    wmma::fragment<wmma::accumulator, 16, 16, 16, float> acc[2][2];
#pragma unroll
    for (int i = 0; i < 2; i++)
#pragma unroll
        for (int j = 0; j < 2; j++) wmma::fill_fragment(acc[i][j], 0.f);

    load_tiles(0, 0);
    for (int k = 0; k < NK; k++) {
        if (k + 1 < NK) load_tiles((k + 1) * BK, (k + 1) & 1);
        __pipeline_wait_prior((k + 1 < NK) ? 1 : 0);
        __syncthreads();
        int buf = k & 1;
        half* sA  = base + buf * ASZ;
        half* sBh = base + 2 * ASZ + buf * BSZ;
        half* sBl = base + 2 * ASZ + 2 * BSZ + buf * BSZ;
#pragma unroll
        for (int kf = 0; kf < 2; kf++) {
            wmma::fragment<wmma::matrix_a, 16, 16, 16, half, wmma::row_major> a[2];
#pragma unroll
            for (int i = 0; i < 2; i++)
                wmma::load_matrix_sync(a[i], sA + (warpM + i * 16) * LDA + kf * 16, LDA);
#pragma unroll
            for (int j = 0; j < 2; j++) {
                wmma::fragment<wmma::matrix_b, 16, 16, 16, half, wmma::row_major> bh, bl;
                wmma::load_matrix_sync(bh, sBh + kf * 16 * LDB + warpN + j * 16, LDB);
                wmma::load_matrix_sync(bl, sBl + kf * 16 * LDB + warpN + j * 16, LDB);
#pragma unroll
                for (int i = 0; i < 2; i++) {
                    wmma::mma_sync(acc[i][j], a[i], bh, acc[i][j]);
                    wmma::mma_sync(acc[i][j], a[i], bl, acc[i][j]);
                }
            }
        }
        __syncthreads();
    }

    // epilogue: stage fp32 -> fp16 mirror + fused logits (direct stores)
#pragma unroll
    for (int i = 0; i < 2; i++)
#pragma unroll
        for (int j = 0; j < 2; j++)
            wmma::store_matrix_sync(Cs + (warpM + i * 16) * LDC + warpN + j * 16,
                                    acc[i][j], LDC, wmma::mem_row_major);
    __syncthreads();
    {
        int cr = t >> 1, cc = (t & 1) * 32;
        int gr = rowBase + cr;
        if (gr < M) {
#pragma unroll
            for (int q = 0; q < 32; q += 2) {
                float x0 = Cs[cr * LDC + cc + q];
                float x1 = Cs[cr * LDC + cc + q + 1];
                *(__half2*)&Ch[(size_t)gr * NOUT + colBase + cc + q] =
                    __floats2half2_rn(x0, x1);
            }
        }
    }
    if (t < BM) {
        int n = rowBase + t;
        if (n < M) {
            int head = colBase / 64;
            const float* Sv = att_s + head * 64;
            const float* Dv = att_d + head * 64;
            const float* row = Cs + t * LDC;
            float s = 0.f, d = 0.f;
#pragma unroll
            for (int c = 0; c < 64; c++) {
                s += row[c] * Sv[c];
                d += row[c] * Dv[c];
            }
            AS[n * HEADS + head] = s;
            AD[n * HEADS + head] = d;
        }
    }
}

// ---------------- per-node softmax (warp per node), writes alpha -------------
__global__ void softmax1_kernel() {
    int w = (blockIdx.x * blockDim.x + threadIdx.x) >> 5;
    int lane = threadIdx.x & 31;
    if (w >= N_NODES) return;
    int lo = g_rowptr[w], hi = g_rowptr[w + 1];
    float4 ad = *(const float4*)&g_ad1[w * 4];
    float m0 = -1e30f, m1 = -1e30f, m2 = -1e30f, m3 = -1e30f;
    float s0 = 0.f, s1 = 0.f, s2 = 0.f, s3 = 0.f;
    for (int k = lo + lane; k < hi; k += 32) {
        int s = g_csr_src[k];
        float4 as = *(const float4*)&g_as1[s * 4];
        float v0 = lrelu(as.x + ad.x), v1 = lrelu(as.y + ad.y);
        float v2 = lrelu(as.z + ad.z), v3 = lrelu(as.w + ad.w);
        if (v0 > m0) { s0 *= __expf(m0 - v0); m0 = v0; }  s0 += __expf(v0 - m0);
        if (v1 > m1) { s1 *= __expf(m1 - v1); m1 = v1; }  s1 += __expf(v1 - m1);
        if (v2 > m2) { s2 *= __expf(m2 - v2); m2 = v2; }  s2 += __expf(v2 - m2);
        if (v3 > m3) { s3 *= __expf(m3 - v3); m3 = v3; }  s3 += __expf(v3 - m3);
    }
#pragma unroll
    for (int off = 16; off; off >>= 1) {
        float mo, so, mn;
        mo = __shfl_xor_sync(0xFFFFFFFFu, m0, off); so = __shfl_xor_sync(0xFFFFFFFFu, s0, off);
        mn = fmaxf(m0, mo); s0 = s0 * __expf(m0 - mn) + so * __expf(mo - mn); m0 = mn;
        mo = __shfl_xor_sync(0xFFFFFFFFu, m1, off); so = __shfl_xor_sync(0xFFFFFFFFu, s1, off);
        mn = fmaxf(m1, mo); s1 = s1 * __expf(m1 - mn) + so * __expf(mo - mn); m1 = mn;
        mo = __shfl_xor_sync(0xFFFFFFFFu, m2, off); so = __shfl_xor_sync(0xFFFFFFFFu, s2, off);
        mn = fmaxf(m2, mo); s2 = s2 * __expf(m2 - mn) + so * __expf(mo - mn); m2 = mn;
        mo = __shfl_xor_sync(0xFFFFFFFFu, m3, off); so = __shfl_xor_sync(0xFFFFFFFFu, s3, off);
        mn = fmaxf(m3, mo); s3 = s3 * __expf(m3 - mn) + so * __expf(mo - mn); m3 = mn;
    }
    float i0 = 1.f / (s0 + EPS_DEN), i1 = 1.f / (s1 + EPS_DEN);
    float i2 = 1.f / (s2 + EPS_DEN), i3 = 1.f / (s3 + EPS_DEN);
    for (int k = lo + lane; k < hi; k += 32) {
        int s = g_csr_src[k];
        float4 as = *(const float4*)&g_as1[s * 4];
        float a0 = __expf(lrelu(as.x + ad.x) - m0) * i0;
        float a1 = __expf(lrelu(as.y + ad.y) - m1) * i1;
        float a2 = __expf(lrelu(as.z + ad.z) - m2) * i2;
        float a3 = __expf(lrelu(as.w + ad.w) - m3) * i3;
        *(float4*)&g_alpha1[k * 4] = make_float4(a0, a1, a2, a3);
    }
}

__global__ void softmax2_kernel() {
    int w = (blockIdx.x * blockDim.x + threadIdx.x) >> 5;
    int lane = threadIdx.x & 31;
    if (w >= N_NODES) return;
    int lo = g_rowptr[w], hi = g_rowptr[w + 1];
    float ad = g_ad2[w];
    float m = -1e30f, s = 0.f;
    for (int k = lo + lane; k < hi; k += 32) {
        float v = lrelu(g_as2[g_csr_src[k]] + ad);
        if (v > m) { s *= __expf(m - v); m = v; }
        s += __expf(v - m);
    }
#pragma unroll
    for (int off = 16; off; off >>= 1) {
        float mo = __shfl_xor_sync(0xFFFFFFFFu, m, off);
        float so = __shfl_xor_sync(0xFFFFFFFFu, s, off);
        float mn = fmaxf(m, mo);
        s = s * __expf(m - mn) + so * __expf(mo - mn);
        m = mn;
    }
    float inv = 1.f / (s + EPS_DEN);
    for (int k = lo + lane; k < hi; k += 32) {
        float v = lrelu(g_as2[g_csr_src[k]] + ad);
        g_alpha2[k] = __expf(v - m) * inv;
    }
}

// ---------------- aggregation (fp16 half2 gathers, 4-way unroll) --------------
__global__ __launch_bounds__(128)
void agg1_kernel(const float* __restrict__ b1) {
    int n = blockIdx.x;
    int c2 = threadIdx.x;
    int h = c2 >> 5;
    int lo = g_rowptr[n], hi = g_rowptr[n + 1];
    const __half2* H = (const __half2*)g_h1h;
    float ax = 0.f, ay = 0.f, bx = 0.f, by = 0.f;
    float cx = 0.f, cy = 0.f, dx = 0.f, dy = 0.f;
    int k = lo;
    for (; k + 3 < hi; k += 4) {
        int s0 = g_csr_src[k],     s1 = g_csr_src[k + 1];
        int s2 = g_csr_src[k + 2], s3 = g_csr_src[k + 3];
        float a0 = g_alpha1[k * 4 + h],       a1 = g_alpha1[(k + 1) * 4 + h];
        float a2 = g_alpha1[(k + 2) * 4 + h], a3 = g_alpha1[(k + 3) * 4 + h];
        float2 v0 = __half22float2(__ldg(&H[(size_t)s0 * 128 + c2]));
        float2 v1 = __half22float2(__ldg(&H[(size_t)s1 * 128 + c2]));
        float2 v2 = __half22float2(__ldg(&H[(size_t)s2 * 128 + c2]));
        float2 v3 = __half22float2(__ldg(&H[(size_t)s3 * 128 + c2]));
        ax += a0 * v0.x; ay += a0 * v0.y;
        bx += a1 * v1.x; by += a1 * v1.y;
        cx += a2 * v2.x; cy += a2 * v2.y;
        dx += a3 * v3.x; dy += a3 * v3.y;
    }
    for (; k < hi; k++) {
        int s0 = g_csr_src[k];
        float a0 = g_alpha1[k * 4 + h];
        float2 v0 = __half22float2(__ldg(&H[(size_t)s0 * 128 + c2]));
        ax += a0 * v0.x; ay += a0 * v0.y;
    }
    float vx = (ax + bx) + (cx + dx) + b1[2 * c2];
    float vy = (ay + by) + (cy + dy) + b1[2 * c2 + 1];
    vx = vx > 0.f ? vx : expm1f(vx);
    vy = vy > 0.f ? vy : expm1f(vy);
    ((__half2*)g_x2h)[((size_t)n * HC1 + 2 * c2) / 2] = __floats2half2_rn(vx, vy);
}

__global__ __launch_bounds__(64)
void agg2_kernel(float* __restrict__ out, const float* __restrict__ b2) {
    int n = blockIdx.x * 2 + (threadIdx.x >> 5);
    if (n >= N_NODES) return;
    int c2 = threadIdx.x & 31;
    int lo = g_rowptr[n], hi = g_rowptr[n + 1];
    const __half2* H = (const __half2*)g_h2h;
    float ax = 0.f, ay = 0.f, bx = 0.f, by = 0.f;
    float cx = 0.f, cy = 0.f, dx = 0.f, dy = 0.f;
    int k = lo;
    for (; k + 3 < hi; k += 4) {
        int s0 = g_csr_src[k],     s1 = g_csr_src[k + 1];
        int s2 = g_csr_src[k + 2], s3 = g_csr_src[k + 3];
        float a0 = g_alpha2[k],     a1 = g_alpha2[k + 1];
        float a2 = g_alpha2[k + 2], a3 = g_alpha2[k + 3];
        float2 v0 = __half22float2(__ldg(&H[(size_t)s0 * 32 + c2]));
        float2 v1 = __half22float2(__ldg(&H[(size_t)s1 * 32 + c2]));
        float2 v2 = __half22float2(__ldg(&H[(size_t)s2 * 32 + c2]));
        float2 v3 = __half22float2(__ldg(&H[(size_t)s3 * 32 + c2]));
        ax += a0 * v0.x; ay += a0 * v0.y;
        bx += a1 * v1.x; by += a1 * v1.y;
        cx += a2 * v2.x; cy += a2 * v2.y;
        dx += a3 * v3.x; dy += a3 * v3.y;
    }
    for (; k < hi; k++) {
        int s0 = g_csr_src[k];
        float a0 = g_alpha2[k];
        float2 v0 = __half22float2(__ldg(&H[(size_t)s0 * 32 + c2]));
        ax += a0 * v0.x; ay += a0 * v0.y;
    }
    float2 r;
    r.x = (ax + bx) + (cx + dx) + b2[2 * c2];
    r.y = (ay + by) + (cy + dy) + b2[2 * c2 + 1];
    *(float2*)&out[(size_t)n * C2 + 2 * c2] = r;
}

// ---------------- launch ------------------------------------------------------
static inline int cdiv(long long a, int b) { return (int)((a + b - 1) / b); }

extern "C" void kernel_launch(void* const* d_in, const int* in_sizes, int n_in,
                              void* d_out, int out_size) {
    const float* x        = (const float*)d_in[0];
    const void*  ei       = d_in[1];
    const float* W1       = (const float*)d_in[2];
    const float* att_src1 = (const float*)d_in[3];
    const float* att_dst1 = (const float*)d_in[4];
    const float* b1       = (const float*)d_in[5];
    const float* W2       = (const float*)d_in[6];
    const float* att_src2 = (const float*)d_in[7];
    const float* att_dst2 = (const float*)d_in[8];
    const float* b2       = (const float*)d_in[9];
    float* out = (float*)d_out;

    float *as1, *ad1, *as2, *ad2;
    __half *xh, *x2h, *h1h, *h2h, *w1h, *w1l, *w2h, *w2l;
    cudaGetSymbolAddress((void**)&xh,  g_xh);
    cudaGetSymbolAddress((void**)&x2h, g_x2h);
    cudaGetSymbolAddress((void**)&h1h, g_h1h);
    cudaGetSymbolAddress((void**)&h2h, g_h2h);
    cudaGetSymbolAddress((void**)&as1, g_as1);
    cudaGetSymbolAddress((void**)&ad1, g_ad1);
    cudaGetSymbolAddress((void**)&as2, g_as2);
    cudaGetSymbolAddress((void**)&ad2, g_ad2);
    cudaGetSymbolAddress((void**)&w1h, g_W1h);
    cudaGetSymbolAddress((void**)&w1l, g_W1l);
    cudaGetSymbolAddress((void**)&w2h, g_W2h);
    cudaGetSymbolAddress((void**)&w2l, g_W2l);

    const int T = 256;
    // smem: tiles = (2*5120 + 4*2304)*2 = 38912 B ; staging = 128*68*4 = 34816 B
    const int SMEM = 38912;

    cudaFuncSetAttribute(hgemm_kernel<F_IN, HC1>,
                         cudaFuncAttributeMaxDynamicSharedMemorySize, SMEM);
    cudaFuncSetAttribute(hgemm_kernel<HC1, C2>,
                         cudaFuncAttributeMaxDynamicSharedMemorySize, SMEM);

    prep_kernel<<<cdiv(F_IN * HC1 + HC1 * C2, T), T>>>(W1, W2);     // #1
    detzero_kernel<<<cdiv(N_NODES, T), T>>>((const int*)ei);        // #2
    xsplit_kernel<<<cdiv((long long)N_NODES * F_IN / 2, T), T>>>(x);// #3
    // #4: hgemm1 — profiled next round
    {
        dim3 grid(HC1 / 64, cdiv(N_NODES, 128));
        hgemm_kernel<F_IN, HC1><<<grid, T, SMEM>>>(
            xh, w1h, w1l, h1h, att_src1, att_dst1, as1, ad1, N_NODES);
    }
    edges_kernel<<<cdiv(ET, T), T>>>(ei);
    scan_partial_kernel<<<NBLK, SCAN_B>>>();
    scan_tops_kernel<<<1, 32>>>();
    scan_final_kernel<<<NBLK, SCAN_B>>>();
    scatter_kernel<<<cdiv(ET, T), T>>>();
    softmax1_kernel<<<cdiv((long long)N_NODES * 32, T), T>>>();
    agg1_kernel<<<N_NODES, 128>>>(b1);
    {
        dim3 grid(C2 / 64, cdiv(N_NODES, 128));
        hgemm_kernel<HC1, C2><<<grid, T, SMEM>>>(
            x2h, w2h, w2l, h2h, att_src2, att_dst2, as2, ad2, N_NODES);
    }
    softmax2_kernel<<<cdiv((long long)N_NODES * 32, T), T>>>();
    agg2_kernel<<<cdiv(N_NODES, 2), 64>>>(out, b2);
}

// round 16
// speedup vs baseline: 1.3840x; 1.0336x over previous
#include <cuda_runtime.h>
#include <cuda_fp16.h>
#include <cuda_pipeline.h>
#include <mma.h>
#include <math.h>
using namespace nvcuda;

#define N_NODES 50000
#define E_EDGES 800000
#define ET      (E_EDGES + N_NODES)   // 850000 edges incl. self loops
#define F_IN    128
#define H1      4
#define C1      64
#define HC1     256
#define C2      64
#define NEG_SLOPE 0.2f
#define EPS_DEN 1e-16f
#define SCAN_B  1024
#define NBLK    ((N_NODES + SCAN_B - 1) / SCAN_B)   // 49

// ---------------- scratch (device globals; 16B-aligned) ----------------------
__device__ __align__(16) __half g_xh [N_NODES * F_IN];  // x fp16
__device__ __align__(16) __half g_h1h[N_NODES * HC1];   // layer1 features (fp16)
__device__ __align__(16) __half g_x2h[N_NODES * HC1];   // elu(agg1+b1) fp16
__device__ __align__(16) __half g_h2h[N_NODES * C2];    // layer2 features (fp16)
__device__ __align__(16) __half g_W1h[F_IN * HC1];      // fp16 weights
__device__ __align__(16) __half g_W2h[HC1 * C2];
__device__ __align__(16) float  g_as1[N_NODES * H1];
__device__ __align__(16) float  g_ad1[N_NODES * H1];
__device__ __align__(16) float  g_as2[N_NODES];
__device__ __align__(16) float  g_ad2[N_NODES];
__device__ __align__(16) float  g_alpha1[ET * H1];
__device__ __align__(16) float  g_alpha2[ET];
__device__ __align__(16) int    g_src[ET];
__device__ __align__(16) int    g_dst[ET];
__device__ __align__(16) int    g_csr_src[ET];
__device__ __align__(16) int    g_rowptr[N_NODES + 1];
__device__ __align__(16) int    g_cursor[N_NODES];
__device__ __align__(16) int    g_deg[N_NODES];
__device__ __align__(16) int    g_bsum[NBLK];
__device__ __align__(16) int    g_boff[NBLK];
__device__ int g_is64;

// ---------------- helpers ----------------------------------------------------
__device__ __forceinline__ int clampN(int v) {
    return v < 0 ? 0 : (v >= N_NODES ? N_NODES - 1 : v);
}
__device__ __forceinline__ float lrelu(float v) {
    return v > 0.f ? v : NEG_SLOPE * v;
}

// ---------------- prep: weights + x -> fp16 -----------------------------------
__global__ void prep_kernel(const float* __restrict__ W1, const float* __restrict__ W2) {
    int i = blockIdx.x * blockDim.x + threadIdx.x;
    if (i < F_IN * HC1) g_W1h[i] = __float2half_rn(W1[i]);
    int j = i - F_IN * HC1;
    if (j >= 0 && j < HC1 * C2) g_W2h[j] = __float2half_rn(W2[j]);
}

__global__ void xsplit_kernel(const float* __restrict__ x) {
    int i = blockIdx.x * blockDim.x + threadIdx.x;
    if (i >= N_NODES * F_IN / 2) return;
    float2 v = *(const float2*)&x[2 * i];
    ((__half2*)g_xh)[i] = __floats2half2_rn(v.x, v.y);
}

// ---------------- detect dtype + zero degree ----------------------------------
__global__ void detzero_kernel(const int* __restrict__ ei32) {
    int i = blockIdx.x * blockDim.x + threadIdx.x;
    if (i < N_NODES) g_deg[i] = 0;
    if (blockIdx.x == 0 && threadIdx.x < 32) {
        int lane = threadIdx.x;
        int v = ei32[2 * lane + 1] | ei32[2 * (lane + 32) + 1] |
                ei32[2 * (lane + 64) + 1] | ei32[2 * (lane + 96) + 1];
#pragma unroll
        for (int o = 16; o; o >>= 1) v |= __shfl_xor_sync(0xFFFFFFFFu, v, o);
        if (lane == 0) g_is64 = (v == 0) ? 1 : 0;
    }
}

__global__ void edges_kernel(const void* __restrict__ ei) {
    int i = blockIdx.x * blockDim.x + threadIdx.x;
    if (i >= ET) return;
    int s, d;
    if (i < E_EDGES) {
        if (g_is64) {
            const long long* p = (const long long*)ei;
            s = (int)p[i];  d = (int)p[E_EDGES + i];
        } else {
            const int* p = (const int*)ei;
            s = p[i];  d = p[E_EDGES + i];
        }
        s = clampN(s); d = clampN(d);
    } else {
        s = d = i - E_EDGES;
    }
    g_src[i] = s;
    g_dst[i] = d;
    atomicAdd(&g_deg[d], 1);
}

// ---------------- 3-phase parallel scan of g_deg -> g_rowptr ------------------
__global__ __launch_bounds__(SCAN_B) void scan_partial_kernel() {
    __shared__ int red[32];
    int i = blockIdx.x * SCAN_B + threadIdx.x;
    int v = (i < N_NODES) ? g_deg[i] : 0;
#pragma unroll
    for (int o = 16; o; o >>= 1) v += __shfl_down_sync(0xFFFFFFFFu, v, o);
    if ((threadIdx.x & 31) == 0) red[threadIdx.x >> 5] = v;
    __syncthreads();
    if (threadIdx.x < 32) {
        int r = red[threadIdx.x];
#pragma unroll
        for (int o = 16; o; o >>= 1) r += __shfl_down_sync(0xFFFFFFFFu, r, o);
        if (threadIdx.x == 0) g_bsum[blockIdx.x] = r;
    }
}

__global__ void scan_tops_kernel() {
    int lane = threadIdx.x;
    int v0 = (lane < NBLK) ? g_bsum[lane] : 0;
    int v1 = (lane + 32 < NBLK) ? g_bsum[lane + 32] : 0;
    int a = v0;
#pragma unroll
    for (int o = 1; o < 32; o <<= 1) {
        int t = __shfl_up_sync(0xFFFFFFFFu, a, o);
        if (lane >= o) a += t;
    }
    int tot0 = __shfl_sync(0xFFFFFFFFu, a, 31);
    int b = v1;
#pragma unroll
    for (int o = 1; o < 32; o <<= 1) {
        int t = __shfl_up_sync(0xFFFFFFFFu, b, o);
        if (lane >= o) b += t;
    }
    b += tot0;
    if (lane < NBLK) g_boff[lane] = a - v0;
    if (lane + 32 < NBLK) g_boff[lane + 32] = b - v1;
    if (lane == 31) g_rowptr[N_NODES] = (NBLK > 32) ? __shfl_sync(0xFFFFFFFFu, b, 31)
                                                    : tot0;
}

__global__ __launch_bounds__(SCAN_B) void scan_final_kernel() {
    __shared__ int warp_tot[32];
    int i = blockIdx.x * SCAN_B + threadIdx.x;
    int v = (i < N_NODES) ? g_deg[i] : 0;
    int lane = threadIdx.x & 31, w = threadIdx.x >> 5;
    int a = v;
#pragma unroll
    for (int o = 1; o < 32; o <<= 1) {
        int t = __shfl_up_sync(0xFFFFFFFFu, a, o);
        if (lane >= o) a += t;
    }
    if (lane == 31) warp_tot[w] = a;
    __syncthreads();
    if (threadIdx.x < 32) {
        int t = warp_tot[threadIdx.x];
        int s = t;
#pragma unroll
        for (int o = 1; o < 32; o <<= 1) {
            int u = __shfl_up_sync(0xFFFFFFFFu, s, o);
            if (threadIdx.x >= o) s += u;
        }
        warp_tot[threadIdx.x] = s - t;
    }
    __syncthreads();
    int excl = a - v + warp_tot[w] + g_boff[blockIdx.x];
    if (i < N_NODES) { g_rowptr[i] = excl; g_cursor[i] = excl; }
}

__global__ void scatter_kernel() {
    int i = blockIdx.x * blockDim.x + threadIdx.x;
    if (i >= ET) return;
    int pos = atomicAdd(&g_cursor[g_dst[i]], 1);
    g_csr_src[pos] = g_src[i];
}

// ---------------- fp16 tensor-core GEMM (fp32 accum) --------------------------
// C = A_fp16 @ B_fp16, fused fp16 mirror + attention logits epilogue.
// Block tile 128x64, 4x2 warps, warp tile 32x32, BK=32, cp.async double-buffer.
template<int K, int NOUT>
__global__ __launch_bounds__(256, 3)
void hgemm_kernel(const __half* __restrict__ Ah,
                  const __half* __restrict__ Bh,
                  __half* __restrict__ Ch,
                  const float* __restrict__ att_s, const float* __restrict__ att_d,
                  float* __restrict__ AS, float* __restrict__ AD, int M) {
    constexpr int BM = 128, BN = 64, BK = 32;
    constexpr int LDA = BK + 8;           // 40 halves
    constexpr int LDB = BN + 8;           // 72 halves
    constexpr int LDC = 68;
    constexpr int ASZ = BM * LDA;         // 5120 halves
    constexpr int BSZ = BK * LDB;         // 2304 halves
    constexpr int NK  = K / BK;
    constexpr int HEADS = NOUT / 64;

    extern __shared__ char smem[];
    half* base = (half*)smem;             // [sA0 sA1 sB0 sB1]
    float* Cs = (float*)smem;             // reused for epilogue staging

    int t = threadIdx.x, wid = t >> 5;
    int wr = wid & 3, wc = wid >> 2;      // 4 x 2 warp grid
    int warpM = wr * 32, warpN = wc * 32;
    int rowBase = blockIdx.y * BM, colBase = blockIdx.x * BN;

    auto load_tiles = [&](int kt, int buf) {
        half* sA = base + buf * ASZ;
        half* sB = base + 2 * ASZ + buf * BSZ;
#pragma unroll
        for (int i = 0; i < 2; i++) {
            int c = t * 2 + i;
            int r = c >> 2, q = (c & 3) * 8;
            int gr = rowBase + r;
            if (gr < M)
                __pipeline_memcpy_async(sA + r * LDA + q,
                                        Ah + (size_t)gr * K + kt + q, 16);
        }
        {
            int r = t >> 3, q = (t & 7) * 8;
            __pipeline_memcpy_async(sB + r * LDB + q,
                                    Bh + (size_t)(kt + r) * NOUT + colBase + q, 16);
        }
        __pipeline_commit();
    };

    wmma::fragment<wmma::accumulator, 16, 16, 16, float> acc[2][2];
#pragma unroll
    for (int i = 0; i < 2; i++)
#pragma unroll
        for (int j = 0; j < 2; j++) wmma::fill_fragment(acc[i][j], 0.f);

    load_tiles(0, 0);
    for (int k = 0; k < NK; k++) {
        if (k + 1 < NK) load_tiles((k + 1) * BK, (k + 1) & 1);
        __pipeline_wait_prior((k + 1 < NK) ? 1 : 0);
        __syncthreads();
        int buf = k & 1;
        half* sA = base + buf * ASZ;
        half* sB = base + 2 * ASZ + buf * BSZ;
#pragma unroll
        for (int kf = 0; kf < 2; kf++) {
            wmma::fragment<wmma::matrix_a, 16, 16, 16, half, wmma::row_major> a[2];
#pragma unroll
            for (int i = 0; i < 2; i++)
                wmma::load_matrix_sync(a[i], sA + (warpM + i * 16) * LDA + kf * 16, LDA);
#pragma unroll
            for (int j = 0; j < 2; j++) {
                wmma::fragment<wmma::matrix_b, 16, 16, 16, half, wmma::row_major> b;
                wmma::load_matrix_sync(b, sB + kf * 16 * LDB + warpN + j * 16, LDB);
#pragma unroll
                for (int i = 0; i < 2; i++)
                    wmma::mma_sync(acc[i][j], a[i], b, acc[i][j]);
            }
        }
        __syncthreads();
    }

    // epilogue: stage fp32 -> fp16 mirror + fused logits (direct stores)
#pragma unroll
    for (int i = 0; i < 2; i++)
#pragma unroll
        for (int j = 0; j < 2; j++)
            wmma::store_matrix_sync(Cs + (warpM + i * 16) * LDC + warpN + j * 16,
                                    acc[i][j], LDC, wmma::mem_row_major);
    __syncthreads();
    {
        int cr = t >> 1, cc = (t & 1) * 32;
        int gr = rowBase + cr;
        if (gr < M) {
#pragma unroll
            for (int q = 0; q < 32; q += 2) {
                float x0 = Cs[cr * LDC + cc + q];
                float x1 = Cs[cr * LDC + cc + q + 1];
                *(__half2*)&Ch[(size_t)gr * NOUT + colBase + cc + q] =
                    __floats2half2_rn(x0, x1);
            }
        }
    }
    if (t < BM) {
        int n = rowBase + t;
        if (n < M) {
            int head = colBase / 64;
            const float* Sv = att_s + head * 64;
            const float* Dv = att_d + head * 64;
            const float* row = Cs + t * LDC;
            float s = 0.f, d = 0.f;
#pragma unroll
            for (int c = 0; c < 64; c++) {
                s += row[c] * Sv[c];
                d += row[c] * Dv[c];
            }
            AS[n * HEADS + head] = s;
            AD[n * HEADS + head] = d;
        }
    }
}

// ---------------- per-node softmax (warp per node), writes alpha -------------
__global__ void softmax1_kernel() {
    int w = (blockIdx.x * blockDim.x + threadIdx.x) >> 5;
    int lane = threadIdx.x & 31;
    if (w >= N_NODES) return;
    int lo = g_rowptr[w], hi = g_rowptr[w + 1];
    float4 ad = *(const float4*)&g_ad1[w * 4];
    float m0 = -1e30f, m1 = -1e30f, m2 = -1e30f, m3 = -1e30f;
    float s0 = 0.f, s1 = 0.f, s2 = 0.f, s3 = 0.f;
    for (int k = lo + lane; k < hi; k += 32) {
        int s = g_csr_src[k];
        float4 as = *(const float4*)&g_as1[s * 4];
        float v0 = lrelu(as.x + ad.x), v1 = lrelu(as.y + ad.y);
        float v2 = lrelu(as.z + ad.z), v3 = lrelu(as.w + ad.w);
        if (v0 > m0) { s0 *= __expf(m0 - v0); m0 = v0; }  s0 += __expf(v0 - m0);
        if (v1 > m1) { s1 *= __expf(m1 - v1); m1 = v1; }  s1 += __expf(v1 - m1);
        if (v2 > m2) { s2 *= __expf(m2 - v2); m2 = v2; }  s2 += __expf(v2 - m2);
        if (v3 > m3) { s3 *= __expf(m3 - v3); m3 = v3; }  s3 += __expf(v3 - m3);
    }
#pragma unroll
    for (int off = 16; off; off >>= 1) {
        float mo, so, mn;
        mo = __shfl_xor_sync(0xFFFFFFFFu, m0, off); so = __shfl_xor_sync(0xFFFFFFFFu, s0, off);
        mn = fmaxf(m0, mo); s0 = s0 * __expf(m0 - mn) + so * __expf(mo - mn); m0 = mn;
        mo = __shfl_xor_sync(0xFFFFFFFFu, m1, off); so = __shfl_xor_sync(0xFFFFFFFFu, s1, off);
        mn = fmaxf(m1, mo); s1 = s1 * __expf(m1 - mn) + so * __expf(mo - mn); m1 = mn;
        mo = __shfl_xor_sync(0xFFFFFFFFu, m2, off); so = __shfl_xor_sync(0xFFFFFFFFu, s2, off);
        mn = fmaxf(m2, mo); s2 = s2 * __expf(m2 - mn) + so * __expf(mo - mn); m2 = mn;
        mo = __shfl_xor_sync(0xFFFFFFFFu, m3, off); so = __shfl_xor_sync(0xFFFFFFFFu, s3, off);
        mn = fmaxf(m3, mo); s3 = s3 * __expf(m3 - mn) + so * __expf(mo - mn); m3 = mn;
    }
    float i0 = 1.f / (s0 + EPS_DEN), i1 = 1.f / (s1 + EPS_DEN);
    float i2 = 1.f / (s2 + EPS_DEN), i3 = 1.f / (s3 + EPS_DEN);
    for (int k = lo + lane; k < hi; k += 32) {
        int s = g_csr_src[k];
        float4 as = *(const float4*)&g_as1[s * 4];
        float a0 = __expf(lrelu(as.x + ad.x) - m0) * i0;
        float a1 = __expf(lrelu(as.y + ad.y) - m1) * i1;
        float a2 = __expf(lrelu(as.z + ad.z) - m2) * i2;
        float a3 = __expf(lrelu(as.w + ad.w) - m3) * i3;
        *(float4*)&g_alpha1[k * 4] = make_float4(a0, a1, a2, a3);
    }
}

__global__ void softmax2_kernel() {
    int w = (blockIdx.x * blockDim.x + threadIdx.x) >> 5;
    int lane = threadIdx.x & 31;
    if (w >= N_NODES) return;
    int lo = g_rowptr[w], hi = g_rowptr[w + 1];
    float ad = g_ad2[w];
    float m = -1e30f, s = 0.f;
    for (int k = lo + lane; k < hi; k += 32) {
        float v = lrelu(g_as2[g_csr_src[k]] + ad);
        if (v > m) { s *= __expf(m - v); m = v; }
        s += __expf(v - m);
    }
#pragma unroll
    for (int off = 16; off; off >>= 1) {
        float mo = __shfl_xor_sync(0xFFFFFFFFu, m, off);
        float so = __shfl_xor_sync(0xFFFFFFFFu, s, off);
        float mn = fmaxf(m, mo);
        s = s * __expf(m - mn) + so * __expf(mo - mn);
        m = mn;
    }
    float inv = 1.f / (s + EPS_DEN);
    for (int k = lo + lane; k < hi; k += 32) {
        float v = lrelu(g_as2[g_csr_src[k]] + ad);
        g_alpha2[k] = __expf(v - m) * inv;
    }
}

// ---------------- aggregation (fp16 half2 gathers, 4-way unroll) --------------
__global__ __launch_bounds__(128)
void agg1_kernel(const float* __restrict__ b1) {
    int n = blockIdx.x;
    int c2 = threadIdx.x;
    int h = c2 >> 5;
    int lo = g_rowptr[n], hi = g_rowptr[n + 1];
    const __half2* H = (const __half2*)g_h1h;
    float ax = 0.f, ay = 0.f, bx = 0.f, by = 0.f;
    float cx = 0.f, cy = 0.f, dx = 0.f, dy = 0.f;
    int k = lo;
    for (; k + 3 < hi; k += 4) {
        int s0 = g_csr_src[k],     s1 = g_csr_src[k + 1];
        int s2 = g_csr_src[k + 2], s3 = g_csr_src[k + 3];
        float a0 = g_alpha1[k * 4 + h],       a1 = g_alpha1[(k + 1) * 4 + h];
        float a2 = g_alpha1[(k + 2) * 4 + h], a3 = g_alpha1[(k + 3) * 4 + h];
        float2 v0 = __half22float2(__ldg(&H[(size_t)s0 * 128 + c2]));
        float2 v1 = __half22float2(__ldg(&H[(size_t)s1 * 128 + c2]));
        float2 v2 = __half22float2(__ldg(&H[(size_t)s2 * 128 + c2]));
        float2 v3 = __half22float2(__ldg(&H[(size_t)s3 * 128 + c2]));
        ax += a0 * v0.x; ay += a0 * v0.y;
        bx += a1 * v1.x; by += a1 * v1.y;
        cx += a2 * v2.x; cy += a2 * v2.y;
        dx += a3 * v3.x; dy += a3 * v3.y;
    }
    for (; k < hi; k++) {
        int s0 = g_csr_src[k];
        float a0 = g_alpha1[k * 4 + h];
        float2 v0 = __half22float2(__ldg(&H[(size_t)s0 * 128 + c2]));
        ax += a0 * v0.x; ay += a0 * v0.y;
    }
    float vx = (ax + bx) + (cx + dx) + b1[2 * c2];
    float vy = (ay + by) + (cy + dy) + b1[2 * c2 + 1];
    vx = vx > 0.f ? vx : expm1f(vx);
    vy = vy > 0.f ? vy : expm1f(vy);
    ((__half2*)g_x2h)[((size_t)n * HC1 + 2 * c2) / 2] = __floats2half2_rn(vx, vy);
}

__global__ __launch_bounds__(64)
void agg2_kernel(float* __restrict__ out, const float* __restrict__ b2) {
    int n = blockIdx.x * 2 + (threadIdx.x >> 5);
    if (n >= N_NODES) return;
    int c2 = threadIdx.x & 31;
    int lo = g_rowptr[n], hi = g_rowptr[n + 1];
    const __half2* H = (const __half2*)g_h2h;
    float ax = 0.f, ay = 0.f, bx = 0.f, by = 0.f;
    float cx = 0.f, cy = 0.f, dx = 0.f, dy = 0.f;
    int k = lo;
    for (; k + 3 < hi; k += 4) {
        int s0 = g_csr_src[k],     s1 = g_csr_src[k + 1];
        int s2 = g_csr_src[k + 2], s3 = g_csr_src[k + 3];
        float a0 = g_alpha2[k],     a1 = g_alpha2[k + 1];
        float a2 = g_alpha2[k + 2], a3 = g_alpha2[k + 3];
        float2 v0 = __half22float2(__ldg(&H[(size_t)s0 * 32 + c2]));
        float2 v1 = __half22float2(__ldg(&H[(size_t)s1 * 32 + c2]));
        float2 v2 = __half22float2(__ldg(&H[(size_t)s2 * 32 + c2]));
        float2 v3 = __half22float2(__ldg(&H[(size_t)s3 * 32 + c2]));
        ax += a0 * v0.x; ay += a0 * v0.y;
        bx += a1 * v1.x; by += a1 * v1.y;
        cx += a2 * v2.x; cy += a2 * v2.y;
        dx += a3 * v3.x; dy += a3 * v3.y;
    }
    for (; k < hi; k++) {
        int s0 = g_csr_src[k];
        float a0 = g_alpha2[k];
        float2 v0 = __half22float2(__ldg(&H[(size_t)s0 * 32 + c2]));
        ax += a0 * v0.x; ay += a0 * v0.y;
    }
    float2 r;
    r.x = (ax + bx) + (cx + dx) + b2[2 * c2];
    r.y = (ay + by) + (cy + dy) + b2[2 * c2 + 1];
    *(float2*)&out[(size_t)n * C2 + 2 * c2] = r;
}

// ---------------- launch ------------------------------------------------------
static inline int cdiv(long long a, int b) { return (int)((a + b - 1) / b); }

extern "C" void kernel_launch(void* const* d_in, const int* in_sizes, int n_in,
                              void* d_out, int out_size) {
    const float* x        = (const float*)d_in[0];
    const void*  ei       = d_in[1];
    const float* W1       = (const float*)d_in[2];
    const float* att_src1 = (const float*)d_in[3];
    const float* att_dst1 = (const float*)d_in[4];
    const float* b1       = (const float*)d_in[5];
    const float* W2       = (const float*)d_in[6];
    const float* att_src2 = (const float*)d_in[7];
    const float* att_dst2 = (const float*)d_in[8];
    const float* b2       = (const float*)d_in[9];
    float* out = (float*)d_out;

    float *as1, *ad1, *as2, *ad2;
    __half *xh, *x2h, *h1h, *h2h, *w1h, *w2h;
    cudaGetSymbolAddress((void**)&xh,  g_xh);
    cudaGetSymbolAddress((void**)&x2h, g_x2h);
    cudaGetSymbolAddress((void**)&h1h, g_h1h);
    cudaGetSymbolAddress((void**)&h2h, g_h2h);
    cudaGetSymbolAddress((void**)&as1, g_as1);
    cudaGetSymbolAddress((void**)&ad1, g_ad1);
    cudaGetSymbolAddress((void**)&as2, g_as2);
    cudaGetSymbolAddress((void**)&ad2, g_ad2);
    cudaGetSymbolAddress((void**)&w1h, g_W1h);
    cudaGetSymbolAddress((void**)&w2h, g_W2h);

    const int T = 256;
    // smem: tiles = (2*5120 + 2*2304)*2 = 29696 B ; staging = 128*68*4 = 34816 B
    const int SMEM = 34816;

    cudaFuncSetAttribute(hgemm_kernel<F_IN, HC1>,
                         cudaFuncAttributeMaxDynamicSharedMemorySize, SMEM);
    cudaFuncSetAttribute(hgemm_kernel<HC1, C2>,
                         cudaFuncAttributeMaxDynamicSharedMemorySize, SMEM);

    prep_kernel<<<cdiv(F_IN * HC1 + HC1 * C2, T), T>>>(W1, W2);     // #1
    detzero_kernel<<<cdiv(N_NODES, T), T>>>((const int*)ei);        // #2
    xsplit_kernel<<<cdiv((long long)N_NODES * F_IN / 2, T), T>>>(x);// #3
    // #4: hgemm1 — profiled next round
    {
        dim3 grid(HC1 / 64, cdiv(N_NODES, 128));
        hgemm_kernel<F_IN, HC1><<<grid, T, SMEM>>>(
            xh, w1h, h1h, att_src1, att_dst1, as1, ad1, N_NODES);
    }
    edges_kernel<<<cdiv(ET, T), T>>>(ei);
    scan_partial_kernel<<<NBLK, SCAN_B>>>();
    scan_tops_kernel<<<1, 32>>>();
    scan_final_kernel<<<NBLK, SCAN_B>>>();
    scatter_kernel<<<cdiv(ET, T), T>>>();
    softmax1_kernel<<<cdiv((long long)N_NODES * 32, T), T>>>();
    agg1_kernel<<<N_NODES, 128>>>(b1);
    {
        dim3 grid(C2 / 64, cdiv(N_NODES, 128));
        hgemm_kernel<HC1, C2><<<grid, T, SMEM>>>(
            x2h, w2h, h2h, att_src2, att_dst2, as2, ad2, N_NODES);
    }
    softmax2_kernel<<<cdiv((long long)N_NODES * 32, T), T>>>();
    agg2_kernel<<<cdiv(N_NODES, 2), 64>>>(out, b2);
}

// round 17
// speedup vs baseline: 1.4296x; 1.0329x over previous
#include <cuda_runtime.h>
#include <cuda_fp16.h>
#include <cuda_pipeline.h>
#include <mma.h>
#include <math.h>
using namespace nvcuda;

#define N_NODES 50000
#define E_EDGES 800000
#define ET      (E_EDGES + N_NODES)   // 850000 edges incl. self loops
#define F_IN    128
#define H1      4
#define C1      64
#define HC1     256
#define C2      64
#define NEG_SLOPE 0.2f
#define EPS_DEN 1e-16f
#define SCAN_B  1024
#define NBLK    ((N_NODES + SCAN_B - 1) / SCAN_B)   // 49

// ---------------- scratch (device globals; 16B-aligned) ----------------------
__device__ __align__(16) __half g_xh [N_NODES * F_IN];  // x fp16
__device__ __align__(16) __half g_h1h[N_NODES * HC1];   // layer1 features (fp16)
__device__ __align__(16) __half g_x2h[N_NODES * HC1];   // elu(agg1+b1) fp16
__device__ __align__(16) __half g_h2h[N_NODES * C2];    // layer2 features (fp16)
__device__ __align__(16) __half g_W1h[F_IN * HC1];      // fp16 weights
__device__ __align__(16) __half g_W2h[HC1 * C2];
__device__ __align__(16) float  g_as1[N_NODES * H1];
__device__ __align__(16) float  g_ad1[N_NODES * H1];
__device__ __align__(16) float  g_as2[N_NODES];
__device__ __align__(16) float  g_ad2[N_NODES];
__device__ __align__(16) float  g_alpha1[ET * H1];
__device__ __align__(16) float  g_alpha2[ET];
__device__ __align__(16) int    g_src[ET];
__device__ __align__(16) int    g_dst[ET];
__device__ __align__(16) int    g_csr_src[ET];
__device__ __align__(16) int    g_rowptr[N_NODES + 1];
__device__ __align__(16) int    g_cursor[N_NODES];
__device__ __align__(16) int    g_deg[N_NODES];
__device__ __align__(16) int    g_bsum[NBLK];
__device__ __align__(16) int    g_boff[NBLK];
__device__ int g_is64;

// ---------------- helpers ----------------------------------------------------
__device__ __forceinline__ int clampN(int v) {
    return v < 0 ? 0 : (v >= N_NODES ? N_NODES - 1 : v);
}
__device__ __forceinline__ float lrelu(float v) {
    return v > 0.f ? v : NEG_SLOPE * v;
}

// ---------------- merged prep: weights->fp16, x->fp16, zero deg, detect -------
__global__ void prep_all_kernel(const float* __restrict__ W1,
                                const float* __restrict__ W2,
                                const float* __restrict__ x,
                                const int* __restrict__ ei32) {
    int i = blockIdx.x * blockDim.x + threadIdx.x;
    if (i < N_NODES * F_IN / 2) {
        float2 v = *(const float2*)&x[2 * i];
        ((__half2*)g_xh)[i] = __floats2half2_rn(v.x, v.y);
    }
    if (i < F_IN * HC1) g_W1h[i] = __float2half_rn(W1[i]);
    if (i < HC1 * C2)   g_W2h[i] = __float2half_rn(W2[i]);
    if (i < N_NODES)    g_deg[i] = 0;
    if (blockIdx.x == 0 && threadIdx.x < 32) {
        int lane = threadIdx.x;
        int v = ei32[2 * lane + 1] | ei32[2 * (lane + 32) + 1] |
                ei32[2 * (lane + 64) + 1] | ei32[2 * (lane + 96) + 1];
#pragma unroll
        for (int o = 16; o; o >>= 1) v |= __shfl_xor_sync(0xFFFFFFFFu, v, o);
        if (lane == 0) g_is64 = (v == 0) ? 1 : 0;
    }
}

__global__ void edges_kernel(const void* __restrict__ ei) {
    int i = blockIdx.x * blockDim.x + threadIdx.x;
    if (i >= ET) return;
    int s, d;
    if (i < E_EDGES) {
        if (g_is64) {
            const long long* p = (const long long*)ei;
            s = (int)p[i];  d = (int)p[E_EDGES + i];
        } else {
            const int* p = (const int*)ei;
            s = p[i];  d = p[E_EDGES + i];
        }
        s = clampN(s); d = clampN(d);
    } else {
        s = d = i - E_EDGES;
    }
    g_src[i] = s;
    g_dst[i] = d;
    atomicAdd(&g_deg[d], 1);
}

// ---------------- 3-phase parallel scan of g_deg -> g_rowptr ------------------
__global__ __launch_bounds__(SCAN_B) void scan_partial_kernel() {
    __shared__ int red[32];
    int i = blockIdx.x * SCAN_B + threadIdx.x;
    int v = (i < N_NODES) ? g_deg[i] : 0;
#pragma unroll
    for (int o = 16; o; o >>= 1) v += __shfl_down_sync(0xFFFFFFFFu, v, o);
    if ((threadIdx.x & 31) == 0) red[threadIdx.x >> 5] = v;
    __syncthreads();
    if (threadIdx.x < 32) {
        int r = red[threadIdx.x];
#pragma unroll
        for (int o = 16; o; o >>= 1) r += __shfl_down_sync(0xFFFFFFFFu, r, o);
        if (threadIdx.x == 0) g_bsum[blockIdx.x] = r;
    }
}

__global__ void scan_tops_kernel() {
    int lane = threadIdx.x;
    int v0 = (lane < NBLK) ? g_bsum[lane] : 0;
    int v1 = (lane + 32 < NBLK) ? g_bsum[lane + 32] : 0;
    int a = v0;
#pragma unroll
    for (int o = 1; o < 32; o <<= 1) {
        int t = __shfl_up_sync(0xFFFFFFFFu, a, o);
        if (lane >= o) a += t;
    }
    int tot0 = __shfl_sync(0xFFFFFFFFu, a, 31);
    int b = v1;
#pragma unroll
    for (int o = 1; o < 32; o <<= 1) {
        int t = __shfl_up_sync(0xFFFFFFFFu, b, o);
        if (lane >= o) b += t;
    }
    b += tot0;
    if (lane < NBLK) g_boff[lane] = a - v0;
    if (lane + 32 < NBLK) g_boff[lane + 32] = b - v1;
    if (lane == 31) g_rowptr[N_NODES] = (NBLK > 32) ? __shfl_sync(0xFFFFFFFFu, b, 31)
                                                    : tot0;
}

__global__ __launch_bounds__(SCAN_B) void scan_final_kernel() {
    __shared__ int warp_tot[32];
    int i = blockIdx.x * SCAN_B + threadIdx.x;
    int v = (i < N_NODES) ? g_deg[i] : 0;
    int lane = threadIdx.x & 31, w = threadIdx.x >> 5;
    int a = v;
#pragma unroll
    for (int o = 1; o < 32; o <<= 1) {
        int t = __shfl_up_sync(0xFFFFFFFFu, a, o);
        if (lane >= o) a += t;
    }
    if (lane == 31) warp_tot[w] = a;
    __syncthreads();
    if (threadIdx.x < 32) {
        int t = warp_tot[threadIdx.x];
        int s = t;
#pragma unroll
        for (int o = 1; o < 32; o <<= 1) {
            int u = __shfl_up_sync(0xFFFFFFFFu, s, o);
            if (threadIdx.x >= o) s += u;
        }
        warp_tot[threadIdx.x] = s - t;
    }
    __syncthreads();
    int excl = a - v + warp_tot[w] + g_boff[blockIdx.x];
    if (i < N_NODES) { g_rowptr[i] = excl; g_cursor[i] = excl; }
}

__global__ void scatter_kernel() {
    int i = blockIdx.x * blockDim.x + threadIdx.x;
    if (i >= ET) return;
    int pos = atomicAdd(&g_cursor[g_dst[i]], 1);
    g_csr_src[pos] = g_src[i];
}

// ---------------- fp16 tensor-core GEMM, single-shot K ------------------------
// Whole 128xK A-strip + Kx64 B-panel loaded once via cp.async; then all K/16
// MMA steps with no further barriers. Fused fp16 mirror + logits epilogue.
template<int K, int NOUT>
__global__ __launch_bounds__(256, 3)
void hgemm_kernel(const __half* __restrict__ Ah,
                  const __half* __restrict__ Bh,
                  __half* __restrict__ Ch,
                  const float* __restrict__ att_s, const float* __restrict__ att_d,
                  float* __restrict__ AS, float* __restrict__ AD, int M) {
    constexpr int BM = 128, BN = 64;
    constexpr int LDA = K + 8;
    constexpr int LDB = BN + 8;           // 72
    constexpr int LDC = 68;
    constexpr int KCH = K / 8;            // 16B chunks per A row
    constexpr int CHA = BM * KCH / 256;   // A chunks per thread (8 / 16)
    constexpr int CHB = K * (BN / 8) / 256;  // B chunks per thread (4 / 8)
    constexpr int HEADS = NOUT / 64;

    extern __shared__ char smem[];
    half* sA = (half*)smem;               // [BM][LDA]
    half* sB = sA + BM * LDA;             // [K][LDB]
    float* Cs = (float*)smem;             // reused for epilogue staging

    int t = threadIdx.x, wid = t >> 5;
    int wr = wid & 3, wc = wid >> 2;      // 4 x 2 warp grid
    int warpM = wr * 32, warpN = wc * 32;
    int rowBase = blockIdx.y * BM, colBase = blockIdx.x * BN;

    // single-shot tile load
#pragma unroll
    for (int i = 0; i < CHA; i++) {
        int c = t + i * 256;
        int r = c / KCH, q = (c % KCH) * 8;
        int gr = rowBase + r;
        if (gr < M)
            __pipeline_memcpy_async(sA + r * LDA + q, Ah + (size_t)gr * K + q, 16);
    }
#pragma unroll
    for (int i = 0; i < CHB; i++) {
        int c = t + i * 256;
        int r = c >> 3, q = (c & 7) * 8;
        __pipeline_memcpy_async(sB + r * LDB + q,
                                Bh + (size_t)r * NOUT + colBase + q, 16);
    }
    __pipeline_commit();

    wmma::fragment<wmma::accumulator, 16, 16, 16, float> acc[2][2];
#pragma unroll
    for (int i = 0; i < 2; i++)
#pragma unroll
        for (int j = 0; j < 2; j++) wmma::fill_fragment(acc[i][j], 0.f);

    __pipeline_wait_prior(0);
    __syncthreads();

#pragma unroll
    for (int kf = 0; kf < K / 16; kf++) {
        wmma::fragment<wmma::matrix_a, 16, 16, 16, half, wmma::row_major> a[2];
#pragma unroll
        for (int i = 0; i < 2; i++)
            wmma::load_matrix_sync(a[i], sA + (warpM + i * 16) * LDA + kf * 16, LDA);
#pragma unroll
        for (int j = 0; j < 2; j++) {
            wmma::fragment<wmma::matrix_b, 16, 16, 16, half, wmma::row_major> b;
            wmma::load_matrix_sync(b, sB + kf * 16 * LDB + warpN + j * 16, LDB);
#pragma unroll
            for (int i = 0; i < 2; i++)
                wmma::mma_sync(acc[i][j], a[i], b, acc[i][j]);
        }
    }
    __syncthreads();

    // epilogue: stage fp32 -> fp16 mirror + fused logits (direct stores)
#pragma unroll
    for (int i = 0; i < 2; i++)
#pragma unroll
        for (int j = 0; j < 2; j++)
            wmma::store_matrix_sync(Cs + (warpM + i * 16) * LDC + warpN + j * 16,
                                    acc[i][j], LDC, wmma::mem_row_major);
    __syncthreads();
    {
        int cr = t >> 1, cc = (t & 1) * 32;
        int gr = rowBase + cr;
        if (gr < M) {
#pragma unroll
            for (int q = 0; q < 32; q += 2) {
                float x0 = Cs[cr * LDC + cc + q];
                float x1 = Cs[cr * LDC + cc + q + 1];
                *(__half2*)&Ch[(size_t)gr * NOUT + colBase + cc + q] =
                    __floats2half2_rn(x0, x1);
            }
        }
    }
    if (t < BM) {
        int n = rowBase + t;
        if (n < M) {
            int head = colBase / 64;
            const float* Sv = att_s + head * 64;
            const float* Dv = att_d + head * 64;
            const float* row = Cs + t * LDC;
            float s = 0.f, d = 0.f;
#pragma unroll
            for (int c = 0; c < 64; c++) {
                s += row[c] * Sv[c];
                d += row[c] * Dv[c];
            }
            AS[n * HEADS + head] = s;
            AD[n * HEADS + head] = d;
        }
    }
}

// ---------------- per-node softmax (warp per node), writes alpha -------------
__global__ void softmax1_kernel() {
    int w = (blockIdx.x * blockDim.x + threadIdx.x) >> 5;
    int lane = threadIdx.x & 31;
    if (w >= N_NODES) return;
    int lo = g_rowptr[w], hi = g_rowptr[w + 1];
    float4 ad = *(const float4*)&g_ad1[w * 4];
    float m0 = -1e30f, m1 = -1e30f, m2 = -1e30f, m3 = -1e30f;
    float s0 = 0.f, s1 = 0.f, s2 = 0.f, s3 = 0.f;
    for (int k = lo + lane; k < hi; k += 32) {
        int s = g_csr_src[k];
        float4 as = *(const float4*)&g_as1[s * 4];
        float v0 = lrelu(as.x + ad.x), v1 = lrelu(as.y + ad.y);
        float v2 = lrelu(as.z + ad.z), v3 = lrelu(as.w + ad.w);
        if (v0 > m0) { s0 *= __expf(m0 - v0); m0 = v0; }  s0 += __expf(v0 - m0);
        if (v1 > m1) { s1 *= __expf(m1 - v1); m1 = v1; }  s1 += __expf(v1 - m1);
        if (v2 > m2) { s2 *= __expf(m2 - v2); m2 = v2; }  s2 += __expf(v2 - m2);
        if (v3 > m3) { s3 *= __expf(m3 - v3); m3 = v3; }  s3 += __expf(v3 - m3);
    }
#pragma unroll
    for (int off = 16; off; off >>= 1) {
        float mo, so, mn;
        mo = __shfl_xor_sync(0xFFFFFFFFu, m0, off); so = __shfl_xor_sync(0xFFFFFFFFu, s0, off);
        mn = fmaxf(m0, mo); s0 = s0 * __expf(m0 - mn) + so * __expf(mo - mn); m0 = mn;
        mo = __shfl_xor_sync(0xFFFFFFFFu, m1, off); so = __shfl_xor_sync(0xFFFFFFFFu, s1, off);
        mn = fmaxf(m1, mo); s1 = s1 * __expf(m1 - mn) + so * __expf(mo - mn); m1 = mn;
        mo = __shfl_xor_sync(0xFFFFFFFFu, m2, off); so = __shfl_xor_sync(0xFFFFFFFFu, s2, off);
        mn = fmaxf(m2, mo); s2 = s2 * __expf(m2 - mn) + so * __expf(mo - mn); m2 = mn;
        mo = __shfl_xor_sync(0xFFFFFFFFu, m3, off); so = __shfl_xor_sync(0xFFFFFFFFu, s3, off);
        mn = fmaxf(m3, mo); s3 = s3 * __expf(m3 - mn) + so * __expf(mo - mn); m3 = mn;
    }
    float i0 = 1.f / (s0 + EPS_DEN), i1 = 1.f / (s1 + EPS_DEN);
    float i2 = 1.f / (s2 + EPS_DEN), i3 = 1.f / (s3 + EPS_DEN);
    for (int k = lo + lane; k < hi; k += 32) {
        int s = g_csr_src[k];
        float4 as = *(const float4*)&g_as1[s * 4];
        float a0 = __expf(lrelu(as.x + ad.x) - m0) * i0;
        float a1 = __expf(lrelu(as.y + ad.y) - m1) * i1;
        float a2 = __expf(lrelu(as.z + ad.z) - m2) * i2;
        float a3 = __expf(lrelu(as.w + ad.w) - m3) * i3;
        *(float4*)&g_alpha1[k * 4] = make_float4(a0, a1, a2, a3);
    }
}

__global__ void softmax2_kernel() {
    int w = (blockIdx.x * blockDim.x + threadIdx.x) >> 5;
    int lane = threadIdx.x & 31;
    if (w >= N_NODES) return;
    int lo = g_rowptr[w], hi = g_rowptr[w + 1];
    float ad = g_ad2[w];
    float m = -1e30f, s = 0.f;
    for (int k = lo + lane; k < hi; k += 32) {
        float v = lrelu(g_as2[g_csr_src[k]] + ad);
        if (v > m) { s *= __expf(m - v); m = v; }
        s += __expf(v - m);
    }
#pragma unroll
    for (int off = 16; off; off >>= 1) {
        float mo = __shfl_xor_sync(0xFFFFFFFFu, m, off);
        float so = __shfl_xor_sync(0xFFFFFFFFu, s, off);
        float mn = fmaxf(m, mo);
        s = s * __expf(m - mn) + so * __expf(mo - mn);
        m = mn;
    }
    float inv = 1.f / (s + EPS_DEN);
    for (int k = lo + lane; k < hi; k += 32) {
        float v = lrelu(g_as2[g_csr_src[k]] + ad);
        g_alpha2[k] = __expf(v - m) * inv;
    }
}

// ---------------- aggregation (fp16 half2 gathers, 4-way unroll) --------------
__global__ __launch_bounds__(128)
void agg1_kernel(const float* __restrict__ b1) {
    int n = blockIdx.x;
    int c2 = threadIdx.x;
    int h = c2 >> 5;
    int lo = g_rowptr[n], hi = g_rowptr[n + 1];
    const __half2* H = (const __half2*)g_h1h;
    float ax = 0.f, ay = 0.f, bx = 0.f, by = 0.f;
    float cx = 0.f, cy = 0.f, dx = 0.f, dy = 0.f;
    int k = lo;
    for (; k + 3 < hi; k += 4) {
        int s0 = g_csr_src[k],     s1 = g_csr_src[k + 1];
        int s2 = g_csr_src[k + 2], s3 = g_csr_src[k + 3];
        float a0 = g_alpha1[k * 4 + h],       a1 = g_alpha1[(k + 1) * 4 + h];
        float a2 = g_alpha1[(k + 2) * 4 + h], a3 = g_alpha1[(k + 3) * 4 + h];
        float2 v0 = __half22float2(__ldg(&H[(size_t)s0 * 128 + c2]));
        float2 v1 = __half22float2(__ldg(&H[(size_t)s1 * 128 + c2]));
        float2 v2 = __half22float2(__ldg(&H[(size_t)s2 * 128 + c2]));
        float2 v3 = __half22float2(__ldg(&H[(size_t)s3 * 128 + c2]));
        ax += a0 * v0.x; ay += a0 * v0.y;
        bx += a1 * v1.x; by += a1 * v1.y;
        cx += a2 * v2.x; cy += a2 * v2.y;
        dx += a3 * v3.x; dy += a3 * v3.y;
    }
    for (; k < hi; k++) {
        int s0 = g_csr_src[k];
        float a0 = g_alpha1[k * 4 + h];
        float2 v0 = __half22float2(__ldg(&H[(size_t)s0 * 128 + c2]));
        ax += a0 * v0.x; ay += a0 * v0.y;
    }
    float vx = (ax + bx) + (cx + dx) + b1[2 * c2];
    float vy = (ay + by) + (cy + dy) + b1[2 * c2 + 1];
    vx = vx > 0.f ? vx : expm1f(vx);
    vy = vy > 0.f ? vy : expm1f(vy);
    ((__half2*)g_x2h)[((size_t)n * HC1 + 2 * c2) / 2] = __floats2half2_rn(vx, vy);
}

__global__ __launch_bounds__(64)
void agg2_kernel(float* __restrict__ out, const float* __restrict__ b2) {
    int n = blockIdx.x * 2 + (threadIdx.x >> 5);
    if (n >= N_NODES) return;
    int c2 = threadIdx.x & 31;
    int lo = g_rowptr[n], hi = g_rowptr[n + 1];
    const __half2* H = (const __half2*)g_h2h;
    float ax = 0.f, ay = 0.f, bx = 0.f, by = 0.f;
    float cx = 0.f, cy = 0.f, dx = 0.f, dy = 0.f;
    int k = lo;
    for (; k + 3 < hi; k += 4) {
        int s0 = g_csr_src[k],     s1 = g_csr_src[k + 1];
        int s2 = g_csr_src[k + 2], s3 = g_csr_src[k + 3];
        float a0 = g_alpha2[k],     a1 = g_alpha2[k + 1];
        float a2 = g_alpha2[k + 2], a3 = g_alpha2[k + 3];
        float2 v0 = __half22float2(__ldg(&H[(size_t)s0 * 32 + c2]));
        float2 v1 = __half22float2(__ldg(&H[(size_t)s1 * 32 + c2]));
        float2 v2 = __half22float2(__ldg(&H[(size_t)s2 * 32 + c2]));
        float2 v3 = __half22float2(__ldg(&H[(size_t)s3 * 32 + c2]));
        ax += a0 * v0.x; ay += a0 * v0.y;
        bx += a1 * v1.x; by += a1 * v1.y;
        cx += a2 * v2.x; cy += a2 * v2.y;
        dx += a3 * v3.x; dy += a3 * v3.y;
    }
    for (; k < hi; k++) {
        int s0 = g_csr_src[k];
        float a0 = g_alpha2[k];
        float2 v0 = __half22float2(__ldg(&H[(size_t)s0 * 32 + c2]));
        ax += a0 * v0.x; ay += a0 * v0.y;
    }
    float2 r;
    r.x = (ax + bx) + (cx + dx) + b2[2 * c2];
    r.y = (ay + by) + (cy + dy) + b2[2 * c2 + 1];
    *(float2*)&out[(size_t)n * C2 + 2 * c2] = r;
}

// ---------------- launch ------------------------------------------------------
static inline int cdiv(long long a, int b) { return (int)((a + b - 1) / b); }

extern "C" void kernel_launch(void* const* d_in, const int* in_sizes, int n_in,
                              void* d_out, int out_size) {
    const float* x        = (const float*)d_in[0];
    const void*  ei       = d_in[1];
    const float* W1       = (const float*)d_in[2];
    const float* att_src1 = (const float*)d_in[3];
    const float* att_dst1 = (const float*)d_in[4];
    const float* b1       = (const float*)d_in[5];
    const float* W2       = (const float*)d_in[6];
    const float* att_src2 = (const float*)d_in[7];
    const float* att_dst2 = (const float*)d_in[8];
    const float* b2       = (const float*)d_in[9];
    float* out = (float*)d_out;

    float *as1, *ad1, *as2, *ad2;
    __half *xh, *x2h, *h1h, *h2h, *w1h, *w2h;
    cudaGetSymbolAddress((void**)&xh,  g_xh);
    cudaGetSymbolAddress((void**)&x2h, g_x2h);
    cudaGetSymbolAddress((void**)&h1h, g_h1h);
    cudaGetSymbolAddress((void**)&h2h, g_h2h);
    cudaGetSymbolAddress((void**)&as1, g_as1);
    cudaGetSymbolAddress((void**)&ad1, g_ad1);
    cudaGetSymbolAddress((void**)&as2, g_as2);
    cudaGetSymbolAddress((void**)&ad2, g_ad2);
    cudaGetSymbolAddress((void**)&w1h, g_W1h);
    cudaGetSymbolAddress((void**)&w2h, g_W2h);

    const int T = 256;
    // layer1: sA 128*136*2 + sB 128*72*2 = 34816+18432 = 53248 (>= 34816 staging)
    // layer2: sA 128*264*2 + sB 256*72*2 = 67584+36864 = 104448
    const int SMEM1 = 53248;
    const int SMEM2 = 104448;

    cudaFuncSetAttribute(hgemm_kernel<F_IN, HC1>,
                         cudaFuncAttributeMaxDynamicSharedMemorySize, SMEM1);
    cudaFuncSetAttribute(hgemm_kernel<HC1, C2>,
                         cudaFuncAttributeMaxDynamicSharedMemorySize, SMEM2);

    prep_all_kernel<<<cdiv((long long)N_NODES * F_IN / 2, T), T>>>(
        W1, W2, x, (const int*)ei);                                 // #1
    edges_kernel<<<cdiv(ET, T), T>>>(ei);                           // #2
    scan_partial_kernel<<<NBLK, SCAN_B>>>();                        // #3
    // #4: hgemm1 — profiled
    {
        dim3 grid(HC1 / 64, cdiv(N_NODES, 128));
        hgemm_kernel<F_IN, HC1><<<grid, T, SMEM1>>>(
            xh, w1h, h1h, att_src1, att_dst1, as1, ad1, N_NODES);
    }
    scan_tops_kernel<<<1, 32>>>();
    scan_final_kernel<<<NBLK, SCAN_B>>>();
    scatter_kernel<<<cdiv(ET, T), T>>>();
    softmax1_kernel<<<cdiv((long long)N_NODES * 32, T), T>>>();
    agg1_kernel<<<N_NODES, 128>>>(b1);
    {
        dim3 grid(C2 / 64, cdiv(N_NODES, 128));
        hgemm_kernel<HC1, C2><<<grid, T, SMEM2>>>(
            x2h, w2h, h2h, att_src2, att_dst2, as2, ad2, N_NODES);
    }
    softmax2_kernel<<<cdiv((long long)N_NODES * 32, T), T>>>();
    agg2_kernel<<<cdiv(N_NODES, 2), 64>>>(out, b2);
}